// round 10
// baseline (speedup 1.0000x reference)
#include <cuda_runtime.h>
#include <math.h>

// Problem constants (fixed shapes per reference)
#define NN 400000
#define EE 3200000
#define S_SEG 1200
#define B_IMG 8

// ---------------- device scratch (static globals; no allocation) ----------------
__device__ __align__(16) float  g_bufA[(size_t)NN * 64];   // h (post-GEMM, pre-BN)
__device__ __align__(16) float  g_bufB[(size_t)NN * 64];   // u = relu(affine(h))*dis
__device__ float  g_dis[NN];                 // rsqrt(deg)
__device__ int    g_degi[NN];
__device__ int    g_rowptr[NN + 1];
__device__ int    g_cursor[NN];
__device__ int    g_csr[EE];                 // src indices grouped by dst
__device__ int    g_bsums[512];
__device__ double g_stats[128];              // per-channel sum / sumsq
__device__ float  g_scale[64];
__device__ float  g_shift[64];
__device__ float  g_segfeat[S_SEG * 256];
__device__ float  g_proj[S_SEG * 64];

// ---------------- packed f32x2 helpers (sm_103a) ----------------
__device__ __forceinline__ unsigned long long f2add(unsigned long long a, unsigned long long b) {
    unsigned long long r;
    asm("add.rn.f32x2 %0, %1, %2;" : "=l"(r) : "l"(a), "l"(b));
    return r;
}
__device__ __forceinline__ unsigned long long f2mul(unsigned long long a, unsigned long long b) {
    unsigned long long r;
    asm("mul.rn.f32x2 %0, %1, %2;" : "=l"(r) : "l"(a), "l"(b));
    return r;
}
__device__ __forceinline__ unsigned long long f2pack(float x) {
    unsigned long long r;
    asm("mov.b64 %0, {%1, %1};" : "=l"(r) : "f"(x));
    return r;
}
__device__ __forceinline__ void f2unpack(unsigned long long v, float& lo, float& hi) {
    asm("mov.b64 {%0, %1}, %2;" : "=f"(lo), "=f"(hi) : "l"(v));
}

// ---------------- degree / CSR build ----------------
__global__ void k_zero_nodes(int n) {
    int i = blockIdx.x * blockDim.x + threadIdx.x;
    if (i < n) { g_degi[i] = 0; g_cursor[i] = 0; }
    if (blockIdx.x == 0 && threadIdx.x < 128) g_stats[threadIdx.x] = 0.0;
}
__global__ void k_deg_count(const int* __restrict__ dst, int e) {
    int i = blockIdx.x * blockDim.x + threadIdx.x;
    if (i < e) atomicAdd(&g_degi[dst[i]], 1);
}

#define SCAN_CHUNK 1024
// scan of degi -> rowptr (block-local) + dis = rsqrt(deg+1) fused
__global__ void k_scan1(int n) {
    __shared__ int sh[256];
    int base = blockIdx.x * SCAN_CHUNK;
    int t = threadIdx.x;
    int v[4]; int loc = 0;
    #pragma unroll
    for (int k = 0; k < 4; k++) {
        int i = base + t * 4 + k;
        v[k] = (i < n) ? g_degi[i] : 0;
        if (i < n) g_dis[i] = rsqrtf((float)(v[k] + 1));
        loc += v[k];
    }
    sh[t] = loc;
    __syncthreads();
    for (int off = 1; off < 256; off <<= 1) {
        int x = sh[t];
        int y = (t >= off) ? sh[t - off] : 0;
        __syncthreads();
        sh[t] = x + y;
        __syncthreads();
    }
    int excl = (t == 0) ? 0 : sh[t - 1];
    if (t == 255) g_bsums[blockIdx.x] = sh[255];
    int run = excl;
    #pragma unroll
    for (int k = 0; k < 4; k++) {
        int i = base + t * 4 + k;
        if (i < n) g_rowptr[i] = run;
        run += v[k];
    }
}
__global__ void k_scan2(int nb) {
    __shared__ int sh[512];
    int t = threadIdx.x;
    sh[t] = (t < nb) ? g_bsums[t] : 0;
    __syncthreads();
    for (int off = 1; off < 512; off <<= 1) {
        int x = sh[t];
        int y = (t >= off) ? sh[t - off] : 0;
        __syncthreads();
        sh[t] = x + y;
        __syncthreads();
    }
    if (t < nb) g_bsums[t] = (t == 0) ? 0 : sh[t - 1];
}
__global__ void k_scan3(int n, int e) {
    int base = blockIdx.x * SCAN_CHUNK;
    int add = g_bsums[blockIdx.x];
    int t = threadIdx.x;
    #pragma unroll
    for (int k = 0; k < 4; k++) {
        int i = base + t * 4 + k;
        if (i < n) g_rowptr[i] += add;
    }
    if (blockIdx.x == 0 && t == 0) g_rowptr[n] = e;
}
__global__ void k_fill(const int* __restrict__ src, const int* __restrict__ dst, int e) {
    int i = blockIdx.x * blockDim.x + threadIdx.x;
    if (i < e) {
        int d = dst[i];
        int p = atomicAdd(&g_cursor[d], 1);
        g_csr[g_rowptr[d] + p] = src[i];
    }
}

// ---------------- prep: u = relu(affine(h)) * dis  (A -> B, streaming) ----------------
template<int D>
__global__ void k_prep(int n) {
    constexpr int NC = D / 4;
    const float4* in = (const float4*)g_bufA;
    float4* out      = (float4*)g_bufB;
    long long tot = (long long)n * NC;
    for (long long idx = (long long)blockIdx.x * blockDim.x + threadIdx.x;
         idx < tot; idx += (long long)gridDim.x * blockDim.x) {
        int node = (int)(idx / NC);
        int f = (int)(idx - (long long)node * NC);
        float dd = g_dis[node];
        float4 sc = ((const float4*)g_scale)[f];
        float4 sh = ((const float4*)g_shift)[f];
        float4 v = in[idx];
        float4 o;
        o.x = fmaxf(fmaf(sc.x, v.x, sh.x), 0.f) * dd;
        o.y = fmaxf(fmaf(sc.y, v.y, sh.y), 0.f) * dd;
        o.z = fmaxf(fmaf(sc.z, v.z, sh.z), 0.f) * dd;
        o.w = fmaxf(fmaf(sc.w, v.w, sh.w), 0.f) * dd;
        out[idx] = o;
    }
}

// ---------------- L1 gather (dim 8, thread-per-node, fused BN stats), B -> A ----------------
__global__ void k_agg8_stats(int n) {
    __shared__ float ss[8], ss2[8];
    int tid = threadIdx.x;
    if (tid < 8) { ss[tid] = 0.f; ss2[tid] = 0.f; }
    __syncthreads();
    const ulonglong2* in = (const ulonglong2*)g_bufB;
    ulonglong2* out      = (ulonglong2*)g_bufA;
    float ls[8], ls2[8];
    #pragma unroll
    for (int c = 0; c < 8; c++) { ls[c] = 0.f; ls2[c] = 0.f; }
    for (int d = blockIdx.x * blockDim.x + threadIdx.x; d < n; d += gridDim.x * blockDim.x) {
        ulonglong2 acc[2];
        acc[0] = in[(size_t)d * 2];
        acc[1] = in[(size_t)d * 2 + 1];
        int beg = g_rowptr[d], end = g_rowptr[d + 1];
        #pragma unroll 2
        for (int j = beg; j < end; j++) {
            int s = g_csr[j];
            ulonglong2 v0 = in[(size_t)s * 2];
            ulonglong2 v1 = in[(size_t)s * 2 + 1];
            acc[0].x = f2add(acc[0].x, v0.x); acc[0].y = f2add(acc[0].y, v0.y);
            acc[1].x = f2add(acc[1].x, v1.x); acc[1].y = f2add(acc[1].y, v1.y);
        }
        unsigned long long dd2 = f2pack(g_dis[d]);
        #pragma unroll
        for (int f = 0; f < 2; f++) {
            acc[f].x = f2mul(acc[f].x, dd2);
            acc[f].y = f2mul(acc[f].y, dd2);
            out[(size_t)d * 2 + f] = acc[f];
            float a, b;
            f2unpack(acc[f].x, a, b);
            ls[f * 4 + 0] += a; ls2[f * 4 + 0] += a * a;
            ls[f * 4 + 1] += b; ls2[f * 4 + 1] += b * b;
            f2unpack(acc[f].y, a, b);
            ls[f * 4 + 2] += a; ls2[f * 4 + 2] += a * a;
            ls[f * 4 + 3] += b; ls2[f * 4 + 3] += b * b;
        }
    }
    #pragma unroll
    for (int c = 0; c < 8; c++) {
        atomicAdd(&ss[c], ls[c]);
        atomicAdd(&ss2[c], ls2[c]);
    }
    __syncthreads();
    if (tid < 8) {
        atomicAdd(&g_stats[tid], (double)ss[tid]);
        atomicAdd(&g_stats[64 + tid], (double)ss2[tid]);
    }
}

// ---------------- fused gather + GEMM + stats: h = agg(u) @ W, B -> A ----------------
// Gather phase: TPN lanes per node accumulate z rows into smem tile.
// GEMM phase: W columns in registers, tile consumed from smem.
template<int FI, int FO>
__global__ void k_aggemm(const float* __restrict__ W, int n) {
    constexpr int TPN = FI / 4;                    // lanes per node (16B each)
    constexpr int NGRP = 256 / TPN;                // concurrent gather groups
    constexpr int TILE = (NGRP > 64) ? NGRP : 64;  // nodes per tile
    constexpr int GPT = TILE / NGRP;               // gather slots per group
    constexpr int NPB = 256 / FO;                  // gemm node-slots per pass
    constexpr int NPT = TILE / NPB;
    __shared__ float xs[TILE * FI];
    const ulonglong2* in = (const ulonglong2*)g_bufB;
    float* hout = g_bufA;
    int tid = threadIdx.x;
    int grp = tid / TPN, lane = tid % TPN;
    int c = tid % FO, gslot = tid / FO;
    float w[FI];
    #pragma unroll
    for (int k = 0; k < FI; k++) w[k] = W[k * FO + c];
    float s1 = 0.f, s2 = 0.f;
    int ntiles = (n + TILE - 1) / TILE;
    ulonglong2* xs2 = (ulonglong2*)xs;
    for (int t = blockIdx.x; t < ntiles; t += gridDim.x) {
        int base = t * TILE;
        __syncthreads();
        // ---- gather phase ----
        #pragma unroll
        for (int g = 0; g < GPT; g++) {
            int slot = grp + g * NGRP;
            int node = base + slot;
            ulonglong2 acc;
            if (node < n) {
                acc = in[(size_t)node * TPN + lane];      // self term u[d]
                int beg = g_rowptr[node], end = g_rowptr[node + 1];
                #pragma unroll 4
                for (int j = beg; j < end; j++) {
                    int s = g_csr[j];
                    ulonglong2 v = in[(size_t)s * TPN + lane];
                    acc.x = f2add(acc.x, v.x);
                    acc.y = f2add(acc.y, v.y);
                }
                unsigned long long dd2 = f2pack(g_dis[node]);
                acc.x = f2mul(acc.x, dd2);
                acc.y = f2mul(acc.y, dd2);
            } else {
                acc.x = 0ull; acc.y = 0ull;
            }
            xs2[slot * TPN + lane] = acc;
        }
        __syncthreads();
        // ---- gemm phase ----
        #pragma unroll
        for (int u = 0; u < NPT; u++) {
            int slot = gslot + u * NPB;
            int node = base + slot;
            if (node < n) {
                float acc = 0.f;
                const float4* row = (const float4*)(xs + slot * FI);
                #pragma unroll
                for (int k4 = 0; k4 < FI / 4; k4++) {
                    float4 z4 = row[k4];
                    acc = fmaf(z4.x, w[k4 * 4 + 0], acc);
                    acc = fmaf(z4.y, w[k4 * 4 + 1], acc);
                    acc = fmaf(z4.z, w[k4 * 4 + 2], acc);
                    acc = fmaf(z4.w, w[k4 * 4 + 3], acc);
                }
                hout[(size_t)node * FO + c] = acc;
                s1 += acc; s2 += acc * acc;
            }
        }
    }
    __shared__ float r1[256], r2[256];
    r1[tid] = s1; r2[tid] = s2;
    __syncthreads();
    if (tid < FO) {
        float a = 0.f, b = 0.f;
        #pragma unroll
        for (int k = 0; k < NPB; k++) { a += r1[k * FO + tid]; b += r2[k * FO + tid]; }
        atomicAdd(&g_stats[tid], (double)a);
        atomicAdd(&g_stats[64 + tid], (double)b);
    }
}

// ---------------- L1 GEMM: u1 = (x @ W1) * dis[node], x -> B ----------------
__global__ void k_gemm1(const float* __restrict__ xin, const float* __restrict__ W, int n) {
    constexpr int FI = 24, FO = 8, TILE = 32;
    constexpr int NPB = 256 / FO;        // 32
    constexpr int NPT = TILE / NPB;      // 1
    __shared__ float xs[TILE * FI];
    int tid = threadIdx.x;
    int c = tid % FO, grp = tid / FO;
    float w[FI];
    #pragma unroll
    for (int k = 0; k < FI; k++) w[k] = W[k * FO + c];
    int ntiles = (n + TILE - 1) / TILE;
    constexpr int NV = TILE * FI / 4;
    for (int t = blockIdx.x; t < ntiles; t += gridDim.x) {
        int base = t * TILE;
        __syncthreads();
        const float4* src4 = (const float4*)(xin + (size_t)base * FI);
        float4* xs4 = (float4*)xs;
        if (base + TILE <= n) {
            #pragma unroll
            for (int i = tid; i < NV; i += 256) xs4[i] = src4[i];
        } else {
            for (int i = tid; i < NV; i += 256) {
                int node = base + (i * 4) / FI;
                xs4[i] = (node < n) ? src4[i] : make_float4(0.f, 0.f, 0.f, 0.f);
            }
        }
        __syncthreads();
        #pragma unroll
        for (int u = 0; u < NPT; u++) {
            int slot = grp + u * NPB;
            int node = base + slot;
            if (node < n) {
                float acc = 0.f;
                const float4* row = (const float4*)(xs + slot * FI);
                #pragma unroll
                for (int k4 = 0; k4 < FI / 4; k4++) {
                    float4 z4 = row[k4];
                    acc = fmaf(z4.x, w[k4 * 4 + 0], acc);
                    acc = fmaf(z4.y, w[k4 * 4 + 1], acc);
                    acc = fmaf(z4.z, w[k4 * 4 + 2], acc);
                    acc = fmaf(z4.w, w[k4 * 4 + 3], acc);
                }
                g_bufB[(size_t)node * FO + c] = acc * g_dis[node];
            }
        }
    }
}

// scale = g*rsqrt(var+eps); shift = be - scale*mean (bias b cancels); zero stats
__global__ void k_bnfin(const float* __restrict__ g, const float* __restrict__ be,
                        int n, int fo) {
    int c = threadIdx.x;
    if (c >= 64) return;
    double s  = g_stats[c];
    double s2 = g_stats[64 + c];
    g_stats[c] = 0.0; g_stats[64 + c] = 0.0;
    if (c < fo) {
        double mean = s / n;
        double var  = s2 / n - mean * mean;
        float rs = rsqrtf((float)var + 1e-5f);
        float sc = g[c] * rs;
        g_scale[c] = sc;
        g_shift[c] = be[c] - sc * (float)mean;
    }
}

// ---------------- segment multi-aggregation (batch_idx sorted, coalesced float4) ----------------
__global__ void k_segagg(const int* __restrict__ bidx, int n) {
    int s = blockIdx.x;
    int tid = threadIdx.x;
    int lane = tid & 15;    // float4 channel chunk
    int rowg = tid >> 4;    // 0..15
    __shared__ int se[2];
    if (tid < 2) {
        int target = s + tid;
        int lo = 0, hi = n;
        while (lo < hi) { int m = (lo + hi) >> 1; if (bidx[m] < target) lo = m + 1; else hi = m; }
        se[tid] = lo;
    }
    __syncthreads();
    int start = se[0], end = se[1];
    float4 sc = ((const float4*)g_scale)[lane];
    float4 sh = ((const float4*)g_shift)[lane];
    float4 sum = make_float4(0.f, 0.f, 0.f, 0.f);
    float4 sum2 = make_float4(0.f, 0.f, 0.f, 0.f);
    float4 mn = make_float4(INFINITY, INFINITY, INFINITY, INFINITY);
    float4 mx = make_float4(-INFINITY, -INFINITY, -INFINITY, -INFINITY);
    const float4* in = (const float4*)g_bufA;
    for (int r = start + rowg; r < end; r += 16) {
        float4 v = in[(size_t)r * 16 + lane];
        float a0 = fmaf(sc.x, v.x, sh.x);
        float a1 = fmaf(sc.y, v.y, sh.y);
        float a2 = fmaf(sc.z, v.z, sh.z);
        float a3 = fmaf(sc.w, v.w, sh.w);
        sum.x += a0; sum2.x += a0 * a0; mn.x = fminf(mn.x, a0); mx.x = fmaxf(mx.x, a0);
        sum.y += a1; sum2.y += a1 * a1; mn.y = fminf(mn.y, a1); mx.y = fmaxf(mx.y, a1);
        sum.z += a2; sum2.z += a2 * a2; mn.z = fminf(mn.z, a2); mx.z = fmaxf(mx.z, a2);
        sum.w += a3; sum2.w += a3 * a3; mn.w = fminf(mn.w, a3); mx.w = fmaxf(mx.w, a3);
    }
    __shared__ float4 rs1[256], rs2[256], rmn[256], rmx[256];
    rs1[tid] = sum; rs2[tid] = sum2; rmn[tid] = mn; rmx[tid] = mx;
    __syncthreads();
    if (rowg == 0) {
        #pragma unroll
        for (int k = 1; k < 16; k++) {
            float4 a = rs1[k * 16 + lane], b = rs2[k * 16 + lane];
            float4 c = rmn[k * 16 + lane], d = rmx[k * 16 + lane];
            sum.x += a.x; sum.y += a.y; sum.z += a.z; sum.w += a.w;
            sum2.x += b.x; sum2.y += b.y; sum2.z += b.z; sum2.w += b.w;
            mn.x = fminf(mn.x, c.x); mn.y = fminf(mn.y, c.y);
            mn.z = fminf(mn.z, c.z); mn.w = fminf(mn.w, c.w);
            mx.x = fmaxf(mx.x, d.x); mx.y = fmaxf(mx.y, d.y);
            mx.z = fmaxf(mx.z, d.z); mx.w = fmaxf(mx.w, d.w);
        }
        float cnt = fmaxf((float)(end - start), 1.0f);
        float inv = 1.0f / cnt;
        float4 mean, stdv;
        mean.x = sum.x * inv; mean.y = sum.y * inv;
        mean.z = sum.z * inv; mean.w = sum.w * inv;
        stdv.x = sqrtf(fmaxf(sum2.x * inv - mean.x * mean.x, 0.f) + 1e-5f);
        stdv.y = sqrtf(fmaxf(sum2.y * inv - mean.y * mean.y, 0.f) + 1e-5f);
        stdv.z = sqrtf(fmaxf(sum2.z * inv - mean.z * mean.z, 0.f) + 1e-5f);
        stdv.w = sqrtf(fmaxf(sum2.w * inv - mean.w * mean.w, 0.f) + 1e-5f);
        float4* sf = (float4*)&g_segfeat[s * 256];
        sf[lane]      = mean;
        sf[16 + lane] = mn;
        sf[32 + lane] = mx;
        sf[48 + lane] = stdv;
    }
}

// ---------------- projection: [S,256] @ Wp[256,64] + bp ----------------
__global__ void k_proj(const float* __restrict__ Wp, const float* __restrict__ bp) {
    int idx = blockIdx.x * blockDim.x + threadIdx.x;
    if (idx >= S_SEG * 64) return;
    int s = idx >> 6, c = idx & 63;
    float acc = bp[c];
    const float* f = &g_segfeat[s * 256];
    #pragma unroll 8
    for (int k = 0; k < 256; k++)
        acc = fmaf(f[k], Wp[k * 64 + c], acc);
    g_proj[idx] = acc;
}

// ---------------- pack: out[b,c,j,i] = proj[offs[b] + i*14+j, c] (masked) ----------------
__global__ void k_pack(const int* __restrict__ num_sp, float* __restrict__ out) {
    int idx = blockIdx.x * blockDim.x + threadIdx.x;
    if (idx >= B_IMG * 64 * 196) return;
    int b   = idx / (64 * 196);
    int rem = idx - b * (64 * 196);
    int c   = rem / 196;
    int ji  = rem - c * 196;
    int j = ji / 14, ii = ji - j * 14;
    int p = ii * 14 + j;
    int ns = num_sp[b];
    int off = 0;
    for (int q = 0; q < b; q++) off += num_sp[q];
    float v = 0.f;
    if (p < ns) {
        int row = off + p;
        if (row > S_SEG - 1) row = S_SEG - 1;
        v = g_proj[row * 64 + c];
    }
    out[idx] = v;
}

// ---------------- host orchestration ----------------
extern "C" void kernel_launch(void* const* d_in, const int* in_sizes, int n_in,
                              void* d_out, int out_size) {
    const float* x        = (const float*)d_in[0];
    const int*   ei       = (const int*)d_in[1];
    const int*   batchidx = (const int*)d_in[2];
    const int*   num_sp   = (const int*)d_in[3];
    const int n = in_sizes[2];
    const int e = in_sizes[1] / 2;
    const int* src = ei;
    const int* dst = ei + e;

    const float* W[5], *g[5], *be[5];
    for (int i = 0; i < 5; i++) {
        W[i]  = (const float*)d_in[4 + 4 * i];
        g[i]  = (const float*)d_in[6 + 4 * i];
        be[i] = (const float*)d_in[7 + 4 * i];
    }
    const float* Wp = (const float*)d_in[24];
    const float* bp = (const float*)d_in[25];
    float* out = (float*)d_out;

    // degrees + CSR build (once per launch)
    k_zero_nodes<<<(n + 255) / 256, 256>>>(n);
    k_deg_count<<<(e + 255) / 256, 256>>>(dst, e);
    int nb = (n + SCAN_CHUNK - 1) / SCAN_CHUNK;
    k_scan1<<<nb, 256>>>(n);
    k_scan2<<<1, 512>>>(nb);
    k_scan3<<<nb, 256>>>(n, e);
    k_fill<<<(e + 255) / 256, 256>>>(src, dst, e);

    const int AB = 1184;

    // L1: GEMM (24->8)*dis -> u1 in B; gather dim8 B->A with stats (h1 in A)
    k_gemm1<<<AB, 256>>>(x, W[0], n);
    k_agg8_stats<<<AB, 256>>>(n);
    k_bnfin<<<1, 64>>>(g[0], be[0], n, 8);

    // L2: prep A->B (dim 8); fused gather+gemm 8->16 B->A
    k_prep<8><<<AB, 256>>>(n);
    k_aggemm<8, 16><<<AB, 256>>>(W[1], n);
    k_bnfin<<<1, 64>>>(g[1], be[1], n, 16);

    // L3: prep A->B (dim 16); fused gather+gemm 16->32 B->A
    k_prep<16><<<AB, 256>>>(n);
    k_aggemm<16, 32><<<AB, 256>>>(W[2], n);
    k_bnfin<<<1, 64>>>(g[2], be[2], n, 32);

    // L4: prep A->B (dim 32); fused gather+gemm 32->64 B->A
    k_prep<32><<<AB, 256>>>(n);
    k_aggemm<32, 64><<<AB, 256>>>(W[3], n);
    k_bnfin<<<1, 64>>>(g[3], be[3], n, 64);

    // L5: prep A->B (dim 64); fused gather+gemm 64->64 B->A (h5 in A)
    k_prep<64><<<AB, 256>>>(n);
    k_aggemm<64, 64><<<AB, 256>>>(W[4], n);
    k_bnfin<<<1, 64>>>(g[4], be[4], n, 64);

    // segment aggregation (applies L5 BN affine, no ReLU)
    k_segagg<<<S_SEG, 256>>>(batchidx, n);
    k_proj<<<(S_SEG * 64 + 255) / 256, 256>>>(Wp, bp);
    k_pack<<<(B_IMG * 64 * 196 + 255) / 256, 256>>>(num_sp, out);
}

// round 12
// speedup vs baseline: 1.1096x; 1.1096x over previous
#include <cuda_runtime.h>
#include <math.h>

// Problem constants (fixed shapes per reference)
#define NN 400000
#define EE 3200000
#define S_SEG 1200
#define B_IMG 8

// ---------------- device scratch (static globals; no allocation) ----------------
__device__ __align__(16) float  g_bufA[(size_t)NN * 64];
__device__ __align__(16) float  g_bufB[(size_t)NN * 64];
__device__ float  g_dis[NN];                 // rsqrt(deg)
__device__ int    g_degi[NN];
__device__ int    g_rowptr[NN + 1];
__device__ int    g_cursor[NN];
__device__ int    g_csr[EE];                 // src indices grouped by dst
__device__ int    g_bsums[512];
__device__ double g_stats[128];              // per-channel sum / sumsq
__device__ float  g_scale[64];
__device__ float  g_shift[64];
__device__ float  g_segfeat[S_SEG * 256];
__device__ float  g_proj[S_SEG * 64];

// ---------------- packed f32x2 helpers (sm_103a) ----------------
__device__ __forceinline__ unsigned long long f2add(unsigned long long a, unsigned long long b) {
    unsigned long long r;
    asm("add.rn.f32x2 %0, %1, %2;" : "=l"(r) : "l"(a), "l"(b));
    return r;
}
__device__ __forceinline__ unsigned long long f2mul(unsigned long long a, unsigned long long b) {
    unsigned long long r;
    asm("mul.rn.f32x2 %0, %1, %2;" : "=l"(r) : "l"(a), "l"(b));
    return r;
}
__device__ __forceinline__ unsigned long long f2pack(float x) {
    unsigned long long r;
    asm("mov.b64 %0, {%1, %1};" : "=l"(r) : "f"(x));
    return r;
}
__device__ __forceinline__ void f2unpack(unsigned long long v, float& lo, float& hi) {
    asm("mov.b64 {%0, %1}, %2;" : "=f"(lo), "=f"(hi) : "l"(v));
}

// ---------------- degree / CSR build ----------------
__global__ void k_zero_nodes(int n) {
    int i = blockIdx.x * blockDim.x + threadIdx.x;
    if (i < n) { g_degi[i] = 0; g_cursor[i] = 0; }
    if (blockIdx.x == 0 && threadIdx.x < 128) g_stats[threadIdx.x] = 0.0;
}
__global__ void k_deg_count(const int* __restrict__ dst, int e) {
    int i = blockIdx.x * blockDim.x + threadIdx.x;
    if (i < e) atomicAdd(&g_degi[dst[i]], 1);
}

#define SCAN_CHUNK 1024
// scan of degi -> rowptr (block-local) + dis = rsqrt(deg+1) fused
__global__ void k_scan1(int n) {
    __shared__ int sh[256];
    int base = blockIdx.x * SCAN_CHUNK;
    int t = threadIdx.x;
    int v[4]; int loc = 0;
    #pragma unroll
    for (int k = 0; k < 4; k++) {
        int i = base + t * 4 + k;
        v[k] = (i < n) ? g_degi[i] : 0;
        if (i < n) g_dis[i] = rsqrtf((float)(v[k] + 1));
        loc += v[k];
    }
    sh[t] = loc;
    __syncthreads();
    for (int off = 1; off < 256; off <<= 1) {
        int x = sh[t];
        int y = (t >= off) ? sh[t - off] : 0;
        __syncthreads();
        sh[t] = x + y;
        __syncthreads();
    }
    int excl = (t == 0) ? 0 : sh[t - 1];
    if (t == 255) g_bsums[blockIdx.x] = sh[255];
    int run = excl;
    #pragma unroll
    for (int k = 0; k < 4; k++) {
        int i = base + t * 4 + k;
        if (i < n) g_rowptr[i] = run;
        run += v[k];
    }
}
__global__ void k_scan2(int nb) {
    __shared__ int sh[512];
    int t = threadIdx.x;
    sh[t] = (t < nb) ? g_bsums[t] : 0;
    __syncthreads();
    for (int off = 1; off < 512; off <<= 1) {
        int x = sh[t];
        int y = (t >= off) ? sh[t - off] : 0;
        __syncthreads();
        sh[t] = x + y;
        __syncthreads();
    }
    if (t < nb) g_bsums[t] = (t == 0) ? 0 : sh[t - 1];
}
__global__ void k_scan3(int n, int e) {
    int base = blockIdx.x * SCAN_CHUNK;
    int add = g_bsums[blockIdx.x];
    int t = threadIdx.x;
    #pragma unroll
    for (int k = 0; k < 4; k++) {
        int i = base + t * 4 + k;
        if (i < n) g_rowptr[i] += add;
    }
    if (blockIdx.x == 0 && t == 0) g_rowptr[n] = e;
}
__global__ void k_fill(const int* __restrict__ src, const int* __restrict__ dst, int e) {
    int i = blockIdx.x * blockDim.x + threadIdx.x;
    if (i < e) {
        int d = dst[i];
        int p = atomicAdd(&g_cursor[d], 1);
        g_csr[g_rowptr[d] + p] = src[i];
    }
}

// ---------------- prep: u = relu(affine(h)) * dis  (A -> B, streaming) ----------------
template<int D, bool IN_A>
__global__ void k_prep(int n) {
    constexpr int NC = D / 4;
    const float4* in = (const float4*)(IN_A ? g_bufA : g_bufB);
    float4* out      = (float4*)(IN_A ? g_bufB : g_bufA);
    long long tot = (long long)n * NC;
    for (long long idx = (long long)blockIdx.x * blockDim.x + threadIdx.x;
         idx < tot; idx += (long long)gridDim.x * blockDim.x) {
        int node = (int)(idx / NC);
        int f = (int)(idx - (long long)node * NC);
        float dd = g_dis[node];
        float4 sc = ((const float4*)g_scale)[f];
        float4 sh = ((const float4*)g_shift)[f];
        float4 v = in[idx];
        float4 o;
        o.x = fmaxf(fmaf(sc.x, v.x, sh.x), 0.f) * dd;
        o.y = fmaxf(fmaf(sc.y, v.y, sh.y), 0.f) * dd;
        o.z = fmaxf(fmaf(sc.z, v.z, sh.z), 0.f) * dd;
        o.w = fmaxf(fmaf(sc.w, v.w, sh.w), 0.f) * dd;
        out[idx] = o;
    }
}

// ---------------- pure-sum gather, thread-per-node (D=8/16), packed adds ----------------
template<int D, bool IN_A, bool STATS>
__global__ void k_agg_tpn(int n) {
    constexpr int NC = D / 4;   // 16B chunks per node
    __shared__ float ss[8], ss2[8];
    int tid = threadIdx.x;
    if (STATS) {
        if (tid < 8) { ss[tid] = 0.f; ss2[tid] = 0.f; }
        __syncthreads();
    }
    const ulonglong2* in = (const ulonglong2*)(IN_A ? g_bufA : g_bufB);
    ulonglong2* out      = (ulonglong2*)(IN_A ? g_bufB : g_bufA);
    float ls[8], ls2[8];
    if (STATS) {
        #pragma unroll
        for (int c = 0; c < 8; c++) { ls[c] = 0.f; ls2[c] = 0.f; }
    }
    for (int d = blockIdx.x * blockDim.x + threadIdx.x; d < n; d += gridDim.x * blockDim.x) {
        ulonglong2 acc[NC];
        #pragma unroll
        for (int f = 0; f < NC; f++) acc[f] = in[(size_t)d * NC + f];   // self term u[d]
        int beg = g_rowptr[d], end = g_rowptr[d + 1];
        #pragma unroll 4
        for (int j = beg; j < end; j++) {
            int s = g_csr[j];
            #pragma unroll
            for (int f = 0; f < NC; f++) {
                ulonglong2 v = in[(size_t)s * NC + f];
                acc[f].x = f2add(acc[f].x, v.x);
                acc[f].y = f2add(acc[f].y, v.y);
            }
        }
        unsigned long long dd2 = f2pack(g_dis[d]);
        #pragma unroll
        for (int f = 0; f < NC; f++) {
            acc[f].x = f2mul(acc[f].x, dd2);
            acc[f].y = f2mul(acc[f].y, dd2);
            out[(size_t)d * NC + f] = acc[f];
            if (STATS) {
                float a, b;
                f2unpack(acc[f].x, a, b);
                ls[f * 4 + 0] += a; ls2[f * 4 + 0] += a * a;
                ls[f * 4 + 1] += b; ls2[f * 4 + 1] += b * b;
                f2unpack(acc[f].y, a, b);
                ls[f * 4 + 2] += a; ls2[f * 4 + 2] += a * a;
                ls[f * 4 + 3] += b; ls2[f * 4 + 3] += b * b;
            }
        }
    }
    if (STATS) {
        #pragma unroll
        for (int c = 0; c < 8; c++) {
            atomicAdd(&ss[c], ls[c]);
            atomicAdd(&ss2[c], ls2[c]);
        }
        __syncthreads();
        if (tid < 8) {
            atomicAdd(&g_stats[tid], (double)ss[tid]);
            atomicAdd(&g_stats[64 + tid], (double)ss2[tid]);
        }
    }
}

// ---------------- pure-sum gather, group variant (D=32/64), dual-node interleave ----------------
// Each lane-group processes TWO adjacent nodes with interleaved edge loops so
// twice as many independent gathers are in flight per group.
template<int D, bool IN_A>
__global__ void k_agg_grp(int n) {
    constexpr int TPN = D / 4;          // lanes per node (16B each)
    constexpr int NPB = 256 / TPN;
    int tid = threadIdx.x;
    int grp = tid / TPN, lane = tid % TPN;
    const ulonglong2* in = (const ulonglong2*)(IN_A ? g_bufA : g_bufB);
    ulonglong2* out      = (ulonglong2*)(IN_A ? g_bufB : g_bufA);
    for (int d0 = (blockIdx.x * NPB + grp) * 2; d0 < n; d0 += gridDim.x * NPB * 2) {
        int d1 = d0 + 1;
        bool has1 = d1 < n;
        ulonglong2 acc0 = in[(size_t)d0 * TPN + lane];   // self term node 0
        ulonglong2 acc1;
        acc1.x = 0ull; acc1.y = 0ull;
        int b0 = g_rowptr[d0];
        int e0 = g_rowptr[d1];           // == rowptr[d0+1]
        int e1 = e0;
        if (has1) {
            acc1 = in[(size_t)d1 * TPN + lane];          // self term node 1
            e1 = g_rowptr[d1 + 1];
        }
        int j0 = b0, j1 = e0;
        int m = min(e0 - j0, e1 - j1);
        #pragma unroll 2
        for (int t = 0; t < m; t++) {
            int s0 = g_csr[j0 + t];
            int s1 = g_csr[j1 + t];
            ulonglong2 v0 = in[(size_t)s0 * TPN + lane];
            ulonglong2 v1 = in[(size_t)s1 * TPN + lane];
            acc0.x = f2add(acc0.x, v0.x); acc0.y = f2add(acc0.y, v0.y);
            acc1.x = f2add(acc1.x, v1.x); acc1.y = f2add(acc1.y, v1.y);
        }
        j0 += m; j1 += m;
        #pragma unroll 4
        for (; j0 < e0; j0++) {
            int s = g_csr[j0];
            ulonglong2 v = in[(size_t)s * TPN + lane];
            acc0.x = f2add(acc0.x, v.x); acc0.y = f2add(acc0.y, v.y);
        }
        #pragma unroll 4
        for (; j1 < e1; j1++) {
            int s = g_csr[j1];
            ulonglong2 v = in[(size_t)s * TPN + lane];
            acc1.x = f2add(acc1.x, v.x); acc1.y = f2add(acc1.y, v.y);
        }
        unsigned long long dd0 = f2pack(g_dis[d0]);
        acc0.x = f2mul(acc0.x, dd0);
        acc0.y = f2mul(acc0.y, dd0);
        out[(size_t)d0 * TPN + lane] = acc0;
        if (has1) {
            unsigned long long dd1 = f2pack(g_dis[d1]);
            acc1.x = f2mul(acc1.x, dd1);
            acc1.y = f2mul(acc1.y, dd1);
            out[(size_t)d1 * TPN + lane] = acc1;
        }
    }
}

// ---------------- GEMM, 32-node tiles, W in registers ----------------
// MODE 0: xin -> bufB, epilogue *dis[node], no stats (layer 1)
// MODE 1: bufA -> bufB, fused BN stats
// MODE 2: bufB -> bufA, fused BN stats
template<int FI, int FO, int MODE>
__global__ void k_gemm2(const float* __restrict__ xin, const float* __restrict__ W, int n) {
    constexpr int TILE = 32;
    constexpr int NPB = 256 / FO;        // node-slots worked concurrently
    constexpr int NPT = TILE / NPB;      // nodes per thread per tile
    __shared__ float xs[TILE * FI];
    const float* zin = (MODE == 0) ? xin : (MODE == 1 ? g_bufA : g_bufB);
    float* hout      = (MODE == 0) ? g_bufB : (MODE == 1 ? g_bufB : g_bufA);
    int tid = threadIdx.x;
    int c = tid % FO, grp = tid / FO;
    float w[FI];
    #pragma unroll
    for (int k = 0; k < FI; k++) w[k] = W[k * FO + c];
    float s1 = 0.f, s2 = 0.f;
    int ntiles = (n + TILE - 1) / TILE;
    constexpr int NV = TILE * FI / 4;
    for (int t = blockIdx.x; t < ntiles; t += gridDim.x) {
        int base = t * TILE;
        __syncthreads();
        const float4* src4 = (const float4*)(zin + (size_t)base * FI);
        float4* xs4 = (float4*)xs;
        if (base + TILE <= n) {
            #pragma unroll
            for (int i = tid; i < NV; i += 256) xs4[i] = src4[i];
        } else {
            for (int i = tid; i < NV; i += 256) {
                int node = base + (i * 4) / FI;
                xs4[i] = (node < n) ? src4[i] : make_float4(0.f, 0.f, 0.f, 0.f);
            }
        }
        __syncthreads();
        #pragma unroll
        for (int u = 0; u < NPT; u++) {
            int slot = grp + u * NPB;
            int node = base + slot;
            if (node < n) {
                float acc = 0.f;
                const float4* row = (const float4*)(xs + slot * FI);
                #pragma unroll
                for (int k4 = 0; k4 < FI / 4; k4++) {
                    float4 z4 = row[k4];
                    acc = fmaf(z4.x, w[k4 * 4 + 0], acc);
                    acc = fmaf(z4.y, w[k4 * 4 + 1], acc);
                    acc = fmaf(z4.z, w[k4 * 4 + 2], acc);
                    acc = fmaf(z4.w, w[k4 * 4 + 3], acc);
                }
                if (MODE == 0) {
                    hout[(size_t)node * FO + c] = acc * g_dis[node];
                } else {
                    hout[(size_t)node * FO + c] = acc;
                    s1 += acc; s2 += acc * acc;
                }
            }
        }
    }
    if (MODE != 0) {
        __shared__ float r1[256], r2[256];
        r1[tid] = s1; r2[tid] = s2;
        __syncthreads();
        if (tid < FO) {
            float a = 0.f, b = 0.f;
            #pragma unroll
            for (int k = 0; k < NPB; k++) { a += r1[k * FO + tid]; b += r2[k * FO + tid]; }
            atomicAdd(&g_stats[tid], (double)a);
            atomicAdd(&g_stats[64 + tid], (double)b);
        }
    }
}

// scale = g*rsqrt(var+eps); shift = be - scale*mean (bias b cancels); zero stats
__global__ void k_bnfin(const float* __restrict__ g, const float* __restrict__ be,
                        int n, int fo) {
    int c = threadIdx.x;
    if (c >= 64) return;
    double s  = g_stats[c];
    double s2 = g_stats[64 + c];
    g_stats[c] = 0.0; g_stats[64 + c] = 0.0;
    if (c < fo) {
        double mean = s / n;
        double var  = s2 / n - mean * mean;
        float rs = rsqrtf((float)var + 1e-5f);
        float sc = g[c] * rs;
        g_scale[c] = sc;
        g_shift[c] = be[c] - sc * (float)mean;
    }
}

// ---------------- segment multi-aggregation (batch_idx sorted, coalesced float4) ----------------
__global__ void k_segagg(const int* __restrict__ bidx, int n) {
    int s = blockIdx.x;
    int tid = threadIdx.x;
    int lane = tid & 15;    // float4 channel chunk: channels 4*lane .. 4*lane+3
    int rowg = tid >> 4;    // 0..15
    __shared__ int se[2];
    if (tid < 2) {
        int target = s + tid;
        int lo = 0, hi = n;
        while (lo < hi) { int m = (lo + hi) >> 1; if (bidx[m] < target) lo = m + 1; else hi = m; }
        se[tid] = lo;
    }
    __syncthreads();
    int start = se[0], end = se[1];
    float4 sc = ((const float4*)g_scale)[lane];
    float4 sh = ((const float4*)g_shift)[lane];
    float4 sum = make_float4(0.f, 0.f, 0.f, 0.f);
    float4 sum2 = make_float4(0.f, 0.f, 0.f, 0.f);
    float4 mn = make_float4(INFINITY, INFINITY, INFINITY, INFINITY);
    float4 mx = make_float4(-INFINITY, -INFINITY, -INFINITY, -INFINITY);
    const float4* in = (const float4*)g_bufA;
    for (int r = start + rowg; r < end; r += 16) {
        float4 v = in[(size_t)r * 16 + lane];
        float a0 = fmaf(sc.x, v.x, sh.x);
        float a1 = fmaf(sc.y, v.y, sh.y);
        float a2 = fmaf(sc.z, v.z, sh.z);
        float a3 = fmaf(sc.w, v.w, sh.w);
        sum.x += a0; sum2.x += a0 * a0; mn.x = fminf(mn.x, a0); mx.x = fmaxf(mx.x, a0);
        sum.y += a1; sum2.y += a1 * a1; mn.y = fminf(mn.y, a1); mx.y = fmaxf(mx.y, a1);
        sum.z += a2; sum2.z += a2 * a2; mn.z = fminf(mn.z, a2); mx.z = fmaxf(mx.z, a2);
        sum.w += a3; sum2.w += a3 * a3; mn.w = fminf(mn.w, a3); mx.w = fmaxf(mx.w, a3);
    }
    __shared__ float4 rs1[256], rs2[256], rmn[256], rmx[256];
    rs1[tid] = sum; rs2[tid] = sum2; rmn[tid] = mn; rmx[tid] = mx;
    __syncthreads();
    if (rowg == 0) {
        #pragma unroll
        for (int k = 1; k < 16; k++) {
            float4 a = rs1[k * 16 + lane], b = rs2[k * 16 + lane];
            float4 c = rmn[k * 16 + lane], d = rmx[k * 16 + lane];
            sum.x += a.x; sum.y += a.y; sum.z += a.z; sum.w += a.w;
            sum2.x += b.x; sum2.y += b.y; sum2.z += b.z; sum2.w += b.w;
            mn.x = fminf(mn.x, c.x); mn.y = fminf(mn.y, c.y);
            mn.z = fminf(mn.z, c.z); mn.w = fminf(mn.w, c.w);
            mx.x = fmaxf(mx.x, d.x); mx.y = fmaxf(mx.y, d.y);
            mx.z = fmaxf(mx.z, d.z); mx.w = fmaxf(mx.w, d.w);
        }
        float cnt = fmaxf((float)(end - start), 1.0f);
        float inv = 1.0f / cnt;
        float4 mean, stdv;
        mean.x = sum.x * inv; mean.y = sum.y * inv;
        mean.z = sum.z * inv; mean.w = sum.w * inv;
        stdv.x = sqrtf(fmaxf(sum2.x * inv - mean.x * mean.x, 0.f) + 1e-5f);
        stdv.y = sqrtf(fmaxf(sum2.y * inv - mean.y * mean.y, 0.f) + 1e-5f);
        stdv.z = sqrtf(fmaxf(sum2.z * inv - mean.z * mean.z, 0.f) + 1e-5f);
        stdv.w = sqrtf(fmaxf(sum2.w * inv - mean.w * mean.w, 0.f) + 1e-5f);
        float4* sf = (float4*)&g_segfeat[s * 256];
        sf[lane]      = mean;
        sf[16 + lane] = mn;
        sf[32 + lane] = mx;
        sf[48 + lane] = stdv;
    }
}

// ---------------- projection: [S,256] @ Wp[256,64] + bp ----------------
__global__ void k_proj(const float* __restrict__ Wp, const float* __restrict__ bp) {
    int idx = blockIdx.x * blockDim.x + threadIdx.x;
    if (idx >= S_SEG * 64) return;
    int s = idx >> 6, c = idx & 63;
    float acc = bp[c];
    const float* f = &g_segfeat[s * 256];
    #pragma unroll 8
    for (int k = 0; k < 256; k++)
        acc = fmaf(f[k], Wp[k * 64 + c], acc);
    g_proj[idx] = acc;
}

// ---------------- pack: out[b,c,j,i] = proj[offs[b] + i*14+j, c] (masked) ----------------
__global__ void k_pack(const int* __restrict__ num_sp, float* __restrict__ out) {
    int idx = blockIdx.x * blockDim.x + threadIdx.x;
    if (idx >= B_IMG * 64 * 196) return;
    int b   = idx / (64 * 196);
    int rem = idx - b * (64 * 196);
    int c   = rem / 196;
    int ji  = rem - c * 196;
    int j = ji / 14, ii = ji - j * 14;
    int p = ii * 14 + j;
    int ns = num_sp[b];
    int off = 0;
    for (int q = 0; q < b; q++) off += num_sp[q];
    float v = 0.f;
    if (p < ns) {
        int row = off + p;
        if (row > S_SEG - 1) row = S_SEG - 1;
        v = g_proj[row * 64 + c];
    }
    out[idx] = v;
}

// ---------------- host orchestration ----------------
extern "C" void kernel_launch(void* const* d_in, const int* in_sizes, int n_in,
                              void* d_out, int out_size) {
    const float* x        = (const float*)d_in[0];
    const int*   ei       = (const int*)d_in[1];
    const int*   batchidx = (const int*)d_in[2];
    const int*   num_sp   = (const int*)d_in[3];
    const int n = in_sizes[2];
    const int e = in_sizes[1] / 2;
    const int* src = ei;
    const int* dst = ei + e;

    const float* W[5], *g[5], *be[5];
    for (int i = 0; i < 5; i++) {
        W[i]  = (const float*)d_in[4 + 4 * i];
        g[i]  = (const float*)d_in[6 + 4 * i];
        be[i] = (const float*)d_in[7 + 4 * i];
    }
    const float* Wp = (const float*)d_in[24];
    const float* bp = (const float*)d_in[25];
    float* out = (float*)d_out;

    // degrees + CSR build (once per launch)
    k_zero_nodes<<<(n + 255) / 256, 256>>>(n);
    k_deg_count<<<(e + 255) / 256, 256>>>(dst, e);
    int nb = (n + SCAN_CHUNK - 1) / SCAN_CHUNK;
    k_scan1<<<nb, 256>>>(n);
    k_scan2<<<1, 512>>>(nb);
    k_scan3<<<nb, 256>>>(n, e);
    k_fill<<<(e + 255) / 256, 256>>>(src, dst, e);

    const int AB = 1184;   // agg/prep grid
    const int GB = 1184;   // gemm grid

    // L1: GEMM (24->8, writes u=t*dis to B), pure-sum agg B->A (stats fused)
    k_gemm2<24, 8, 0><<<GB, 256>>>(x, W[0], n);
    k_agg_tpn<8, false, true><<<AB, 256>>>(n);
    k_bnfin<<<1, 64>>>(g[0], be[0], n, 8);

    // L2: prep A->B (dim 8), agg B->A, gemm 8->16 A->B
    k_prep<8, true><<<AB, 256>>>(n);
    k_agg_tpn<8, false, false><<<AB, 256>>>(n);
    k_gemm2<8, 16, 1><<<GB, 256>>>(nullptr, W[1], n);
    k_bnfin<<<1, 64>>>(g[1], be[1], n, 16);

    // L3: prep B->A (dim 16), agg A->B, gemm 16->32 B->A
    k_prep<16, false><<<AB, 256>>>(n);
    k_agg_tpn<16, true, false><<<AB, 256>>>(n);
    k_gemm2<16, 32, 2><<<GB, 256>>>(nullptr, W[2], n);
    k_bnfin<<<1, 64>>>(g[2], be[2], n, 32);

    // L4: prep A->B (dim 32), agg B->A, gemm 32->64 A->B
    k_prep<32, true><<<AB, 256>>>(n);
    k_agg_grp<32, false><<<AB, 256>>>(n);
    k_gemm2<32, 64, 1><<<GB, 256>>>(nullptr, W[3], n);
    k_bnfin<<<1, 64>>>(g[3], be[3], n, 64);

    // L5: prep B->A (dim 64), agg A->B, gemm 64->64 B->A  (h5 in A)
    k_prep<64, false><<<AB, 256>>>(n);
    k_agg_grp<64, true><<<AB, 256>>>(n);
    k_gemm2<64, 64, 2><<<GB, 256>>>(nullptr, W[4], n);
    k_bnfin<<<1, 64>>>(g[4], be[4], n, 64);

    // segment aggregation (applies L5 BN affine, no ReLU)
    k_segagg<<<S_SEG, 256>>>(batchidx, n);
    k_proj<<<(S_SEG * 64 + 255) / 256, 256>>>(Wp, bp);
    k_pack<<<(B_IMG * 64 * 196 + 255) / 256, 256>>>(num_sp, out);
}

// round 13
// speedup vs baseline: 1.1583x; 1.0438x over previous
#include <cuda_runtime.h>
#include <math.h>

// Problem constants (fixed shapes per reference)
#define NN 400000
#define EE 3200000
#define S_SEG 1200
#define B_IMG 8

// ---------------- device scratch (static globals; no allocation) ----------------
__device__ __align__(16) float  g_bufA[(size_t)NN * 64];
__device__ __align__(16) float  g_bufB[(size_t)NN * 64];
__device__ float  g_dis[NN];                 // rsqrt(deg)
__device__ int    g_degi[NN];
__device__ int    g_rowptr[NN + 1];
__device__ int    g_cursor[NN];
__device__ int    g_csr[EE];                 // src indices grouped by dst
__device__ int    g_bsums[512];
__device__ double g_stats[5 * 128];          // per-layer: [slot][sum(64) | sumsq(64)]
__device__ float  g_segfeat[S_SEG * 256];
__device__ float  g_proj[S_SEG * 64];

// ---------------- packed f32x2 helpers (sm_103a) ----------------
__device__ __forceinline__ unsigned long long f2add(unsigned long long a, unsigned long long b) {
    unsigned long long r;
    asm("add.rn.f32x2 %0, %1, %2;" : "=l"(r) : "l"(a), "l"(b));
    return r;
}
__device__ __forceinline__ unsigned long long f2mul(unsigned long long a, unsigned long long b) {
    unsigned long long r;
    asm("mul.rn.f32x2 %0, %1, %2;" : "=l"(r) : "l"(a), "l"(b));
    return r;
}
__device__ __forceinline__ unsigned long long f2pack(float x) {
    unsigned long long r;
    asm("mov.b64 %0, {%1, %1};" : "=l"(r) : "f"(x));
    return r;
}
__device__ __forceinline__ void f2unpack(unsigned long long v, float& lo, float& hi) {
    asm("mov.b64 {%0, %1}, %2;" : "=f"(lo), "=f"(hi) : "l"(v));
}

// BN fold: scale = g*rsqrt(var+eps); shift = be - scale*mean (bias b cancels)
__device__ __forceinline__ void bn_affine(int slot, int c, int n,
                                          const float* gg, const float* bee,
                                          float& sc, float& sh) {
    double s  = g_stats[slot * 128 + c];
    double s2 = g_stats[slot * 128 + 64 + c];
    double mean = s / n;
    double var  = s2 / n - mean * mean;
    float rs = rsqrtf((float)var + 1e-5f);
    sc = gg[c] * rs;
    sh = bee[c] - sc * (float)mean;
}

// ---------------- degree / CSR build ----------------
__global__ void k_zero_nodes(int n) {
    int i = blockIdx.x * blockDim.x + threadIdx.x;
    if (i < n) g_degi[i] = 0;
    if (i < 5 * 128) g_stats[i] = 0.0;
}
__global__ void k_deg_count(const int* __restrict__ dst, int e) {
    int i = blockIdx.x * blockDim.x + threadIdx.x;
    if (i < e) atomicAdd(&g_degi[dst[i]], 1);
}

#define SCAN_CHUNK 1024
// scan of degi -> rowptr (block-local) + dis = rsqrt(deg+1) fused
__global__ void k_scan1(int n) {
    __shared__ int sh[256];
    int base = blockIdx.x * SCAN_CHUNK;
    int t = threadIdx.x;
    int v[4]; int loc = 0;
    #pragma unroll
    for (int k = 0; k < 4; k++) {
        int i = base + t * 4 + k;
        v[k] = (i < n) ? g_degi[i] : 0;
        if (i < n) g_dis[i] = rsqrtf((float)(v[k] + 1));
        loc += v[k];
    }
    sh[t] = loc;
    __syncthreads();
    for (int off = 1; off < 256; off <<= 1) {
        int x = sh[t];
        int y = (t >= off) ? sh[t - off] : 0;
        __syncthreads();
        sh[t] = x + y;
        __syncthreads();
    }
    int excl = (t == 0) ? 0 : sh[t - 1];
    if (t == 255) g_bsums[blockIdx.x] = sh[255];
    int run = excl;
    #pragma unroll
    for (int k = 0; k < 4; k++) {
        int i = base + t * 4 + k;
        if (i < n) g_rowptr[i] = run;
        run += v[k];
    }
}
__global__ void k_scan2(int nb) {
    __shared__ int sh[512];
    int t = threadIdx.x;
    sh[t] = (t < nb) ? g_bsums[t] : 0;
    __syncthreads();
    for (int off = 1; off < 512; off <<= 1) {
        int x = sh[t];
        int y = (t >= off) ? sh[t - off] : 0;
        __syncthreads();
        sh[t] = x + y;
        __syncthreads();
    }
    if (t < nb) g_bsums[t] = (t == 0) ? 0 : sh[t - 1];
}
// finalize rowptr; also copy into cursor so k_fill's atomicAdd yields absolute slots
__global__ void k_scan3(int n, int e) {
    int base = blockIdx.x * SCAN_CHUNK;
    int add = g_bsums[blockIdx.x];
    int t = threadIdx.x;
    #pragma unroll
    for (int k = 0; k < 4; k++) {
        int i = base + t * 4 + k;
        if (i < n) {
            int r = g_rowptr[i] + add;
            g_rowptr[i] = r;
            g_cursor[i] = r;
        }
    }
    if (blockIdx.x == 0 && t == 0) g_rowptr[n] = e;
}
__global__ void k_fill(const int* __restrict__ src, const int* __restrict__ dst, int e) {
    int i = blockIdx.x * blockDim.x + threadIdx.x;
    if (i < e) {
        int p = atomicAdd(&g_cursor[dst[i]], 1);
        g_csr[p] = src[i];
    }
}

// ---------------- prep: u = relu(affine(h)) * dis  (streaming; affine from stats slot) ----------------
template<int D, bool IN_A>
__global__ void k_prep(int n, const float* __restrict__ gg, const float* __restrict__ bee,
                       int slot) {
    constexpr int NC = D / 4;
    __shared__ __align__(16) float sc_s[D], sh_s[D];
    int t = threadIdx.x;
    if (t < D) {
        float sc, sh;
        bn_affine(slot, t, n, gg, bee, sc, sh);
        sc_s[t] = sc; sh_s[t] = sh;
    }
    __syncthreads();
    const float4* in = (const float4*)(IN_A ? g_bufA : g_bufB);
    float4* out      = (float4*)(IN_A ? g_bufB : g_bufA);
    const float4* sc4 = (const float4*)sc_s;
    const float4* sh4 = (const float4*)sh_s;
    long long tot = (long long)n * NC;
    for (long long idx = (long long)blockIdx.x * blockDim.x + threadIdx.x;
         idx < tot; idx += (long long)gridDim.x * blockDim.x) {
        int node = (int)(idx / NC);
        int f = (int)(idx - (long long)node * NC);
        float dd = g_dis[node];
        float4 sc = sc4[f];
        float4 sh = sh4[f];
        float4 v = in[idx];
        float4 o;
        o.x = fmaxf(fmaf(sc.x, v.x, sh.x), 0.f) * dd;
        o.y = fmaxf(fmaf(sc.y, v.y, sh.y), 0.f) * dd;
        o.z = fmaxf(fmaf(sc.z, v.z, sh.z), 0.f) * dd;
        o.w = fmaxf(fmaf(sc.w, v.w, sh.w), 0.f) * dd;
        out[idx] = o;
    }
}

// ---------------- pure-sum gather, thread-per-node (D=8/16), packed adds ----------------
template<int D, bool IN_A, bool STATS>
__global__ void k_agg_tpn(int n) {
    constexpr int NC = D / 4;   // 16B chunks per node
    __shared__ float ss[8], ss2[8];
    int tid = threadIdx.x;
    if (STATS) {
        if (tid < 8) { ss[tid] = 0.f; ss2[tid] = 0.f; }
        __syncthreads();
    }
    const ulonglong2* in = (const ulonglong2*)(IN_A ? g_bufA : g_bufB);
    ulonglong2* out      = (ulonglong2*)(IN_A ? g_bufB : g_bufA);
    float ls[8], ls2[8];
    if (STATS) {
        #pragma unroll
        for (int c = 0; c < 8; c++) { ls[c] = 0.f; ls2[c] = 0.f; }
    }
    for (int d = blockIdx.x * blockDim.x + threadIdx.x; d < n; d += gridDim.x * blockDim.x) {
        ulonglong2 acc[NC];
        #pragma unroll
        for (int f = 0; f < NC; f++) acc[f] = in[(size_t)d * NC + f];   // self term u[d]
        int beg = g_rowptr[d], end = g_rowptr[d + 1];
        #pragma unroll 2
        for (int j = beg; j < end; j++) {
            int s = g_csr[j];
            #pragma unroll
            for (int f = 0; f < NC; f++) {
                ulonglong2 v = in[(size_t)s * NC + f];
                acc[f].x = f2add(acc[f].x, v.x);
                acc[f].y = f2add(acc[f].y, v.y);
            }
        }
        unsigned long long dd2 = f2pack(g_dis[d]);
        #pragma unroll
        for (int f = 0; f < NC; f++) {
            acc[f].x = f2mul(acc[f].x, dd2);
            acc[f].y = f2mul(acc[f].y, dd2);
            out[(size_t)d * NC + f] = acc[f];
            if (STATS) {
                float a, b;
                f2unpack(acc[f].x, a, b);
                ls[f * 4 + 0] += a; ls2[f * 4 + 0] += a * a;
                ls[f * 4 + 1] += b; ls2[f * 4 + 1] += b * b;
                f2unpack(acc[f].y, a, b);
                ls[f * 4 + 2] += a; ls2[f * 4 + 2] += a * a;
                ls[f * 4 + 3] += b; ls2[f * 4 + 3] += b * b;
            }
        }
    }
    if (STATS) {
        #pragma unroll
        for (int c = 0; c < 8; c++) {
            atomicAdd(&ss[c], ls[c]);
            atomicAdd(&ss2[c], ls2[c]);
        }
        __syncthreads();
        if (tid < 8) {
            atomicAdd(&g_stats[tid], (double)ss[tid]);          // slot 0
            atomicAdd(&g_stats[64 + tid], (double)ss2[tid]);
        }
    }
}

// ---------------- pure-sum gather, group variant (D=32/64), packed adds ----------------
template<int D, bool IN_A>
__global__ void k_agg_grp(int n) {
    constexpr int TPN = D / 4;          // lanes per node (16B each)
    constexpr int NPB = 256 / TPN;
    int tid = threadIdx.x;
    int grp = tid / TPN, lane = tid % TPN;
    const ulonglong2* in = (const ulonglong2*)(IN_A ? g_bufA : g_bufB);
    ulonglong2* out      = (ulonglong2*)(IN_A ? g_bufB : g_bufA);
    for (int d = blockIdx.x * NPB + grp; d < n; d += gridDim.x * NPB) {
        ulonglong2 acc = in[(size_t)d * TPN + lane];   // self term
        int beg = g_rowptr[d], end = g_rowptr[d + 1];
        #pragma unroll 4
        for (int j = beg; j < end; j++) {
            int s = g_csr[j];
            ulonglong2 v = in[(size_t)s * TPN + lane];
            acc.x = f2add(acc.x, v.x);
            acc.y = f2add(acc.y, v.y);
        }
        unsigned long long dd2 = f2pack(g_dis[d]);
        acc.x = f2mul(acc.x, dd2);
        acc.y = f2mul(acc.y, dd2);
        out[(size_t)d * TPN + lane] = acc;
    }
}

// ---------------- GEMM, 32-node tiles, W in registers ----------------
// MODE 0: xin -> bufB, epilogue *dis[node], no stats (layer 1)
// MODE 1: bufA -> bufB, fused BN stats -> slot
// MODE 2: bufB -> bufA, fused BN stats -> slot
template<int FI, int FO, int MODE>
__global__ void k_gemm2(const float* __restrict__ xin, const float* __restrict__ W,
                        int n, int slot) {
    constexpr int TILE = 32;
    constexpr int NPB = 256 / FO;        // node-slots worked concurrently
    constexpr int NPT = TILE / NPB;      // nodes per thread per tile
    __shared__ float xs[TILE * FI];
    const float* zin = (MODE == 0) ? xin : (MODE == 1 ? g_bufA : g_bufB);
    float* hout      = (MODE == 0) ? g_bufB : (MODE == 1 ? g_bufB : g_bufA);
    int tid = threadIdx.x;
    int c = tid % FO, grp = tid / FO;
    float w[FI];
    #pragma unroll
    for (int k = 0; k < FI; k++) w[k] = W[k * FO + c];
    float s1 = 0.f, s2 = 0.f;
    int ntiles = (n + TILE - 1) / TILE;
    constexpr int NV = TILE * FI / 4;
    for (int t = blockIdx.x; t < ntiles; t += gridDim.x) {
        int base = t * TILE;
        __syncthreads();
        const float4* src4 = (const float4*)(zin + (size_t)base * FI);
        float4* xs4 = (float4*)xs;
        if (base + TILE <= n) {
            #pragma unroll
            for (int i = tid; i < NV; i += 256) xs4[i] = src4[i];
        } else {
            for (int i = tid; i < NV; i += 256) {
                int node = base + (i * 4) / FI;
                xs4[i] = (node < n) ? src4[i] : make_float4(0.f, 0.f, 0.f, 0.f);
            }
        }
        __syncthreads();
        #pragma unroll
        for (int u = 0; u < NPT; u++) {
            int slotn = grp + u * NPB;
            int node = base + slotn;
            if (node < n) {
                float acc = 0.f;
                const float4* row = (const float4*)(xs + slotn * FI);
                #pragma unroll
                for (int k4 = 0; k4 < FI / 4; k4++) {
                    float4 z4 = row[k4];
                    acc = fmaf(z4.x, w[k4 * 4 + 0], acc);
                    acc = fmaf(z4.y, w[k4 * 4 + 1], acc);
                    acc = fmaf(z4.z, w[k4 * 4 + 2], acc);
                    acc = fmaf(z4.w, w[k4 * 4 + 3], acc);
                }
                if (MODE == 0) {
                    hout[(size_t)node * FO + c] = acc * g_dis[node];
                } else {
                    hout[(size_t)node * FO + c] = acc;
                    s1 += acc; s2 += acc * acc;
                }
            }
        }
    }
    if (MODE != 0) {
        __shared__ float r1[256], r2[256];
        r1[tid] = s1; r2[tid] = s2;
        __syncthreads();
        if (tid < FO) {
            float a = 0.f, b = 0.f;
            #pragma unroll
            for (int k = 0; k < NPB; k++) { a += r1[k * FO + tid]; b += r2[k * FO + tid]; }
            atomicAdd(&g_stats[slot * 128 + tid], (double)a);
            atomicAdd(&g_stats[slot * 128 + 64 + tid], (double)b);
        }
    }
}

// ---------------- segment multi-aggregation (batch_idx sorted, coalesced float4) ----------------
// Applies layer-5 BN affine computed in-block from stats slot 4.
__global__ void k_segagg(const int* __restrict__ bidx, int n,
                         const float* __restrict__ gg, const float* __restrict__ bee) {
    int s = blockIdx.x;
    int tid = threadIdx.x;
    int lane = tid & 15;    // float4 channel chunk
    int rowg = tid >> 4;    // 0..15
    __shared__ int se[2];
    __shared__ __align__(16) float sc_s[64], sh_s[64];
    if (tid < 2) {
        int target = s + tid;
        int lo = 0, hi = n;
        while (lo < hi) { int m = (lo + hi) >> 1; if (bidx[m] < target) lo = m + 1; else hi = m; }
        se[tid] = lo;
    }
    if (tid < 64) {
        float sc, sh;
        bn_affine(4, tid, n, gg, bee, sc, sh);
        sc_s[tid] = sc; sh_s[tid] = sh;
    }
    __syncthreads();
    int start = se[0], end = se[1];
    float4 sc = ((const float4*)sc_s)[lane];
    float4 sh = ((const float4*)sh_s)[lane];
    float4 sum = make_float4(0.f, 0.f, 0.f, 0.f);
    float4 sum2 = make_float4(0.f, 0.f, 0.f, 0.f);
    float4 mn = make_float4(INFINITY, INFINITY, INFINITY, INFINITY);
    float4 mx = make_float4(-INFINITY, -INFINITY, -INFINITY, -INFINITY);
    const float4* in = (const float4*)g_bufA;
    for (int r = start + rowg; r < end; r += 16) {
        float4 v = in[(size_t)r * 16 + lane];
        float a0 = fmaf(sc.x, v.x, sh.x);
        float a1 = fmaf(sc.y, v.y, sh.y);
        float a2 = fmaf(sc.z, v.z, sh.z);
        float a3 = fmaf(sc.w, v.w, sh.w);
        sum.x += a0; sum2.x += a0 * a0; mn.x = fminf(mn.x, a0); mx.x = fmaxf(mx.x, a0);
        sum.y += a1; sum2.y += a1 * a1; mn.y = fminf(mn.y, a1); mx.y = fmaxf(mx.y, a1);
        sum.z += a2; sum2.z += a2 * a2; mn.z = fminf(mn.z, a2); mx.z = fmaxf(mx.z, a2);
        sum.w += a3; sum2.w += a3 * a3; mn.w = fminf(mn.w, a3); mx.w = fmaxf(mx.w, a3);
    }
    __shared__ float4 rs1[256], rs2[256], rmn[256], rmx[256];
    rs1[tid] = sum; rs2[tid] = sum2; rmn[tid] = mn; rmx[tid] = mx;
    __syncthreads();
    if (rowg == 0) {
        #pragma unroll
        for (int k = 1; k < 16; k++) {
            float4 a = rs1[k * 16 + lane], b = rs2[k * 16 + lane];
            float4 c = rmn[k * 16 + lane], d = rmx[k * 16 + lane];
            sum.x += a.x; sum.y += a.y; sum.z += a.z; sum.w += a.w;
            sum2.x += b.x; sum2.y += b.y; sum2.z += b.z; sum2.w += b.w;
            mn.x = fminf(mn.x, c.x); mn.y = fminf(mn.y, c.y);
            mn.z = fminf(mn.z, c.z); mn.w = fminf(mn.w, c.w);
            mx.x = fmaxf(mx.x, d.x); mx.y = fmaxf(mx.y, d.y);
            mx.z = fmaxf(mx.z, d.z); mx.w = fmaxf(mx.w, d.w);
        }
        float cnt = fmaxf((float)(end - start), 1.0f);
        float inv = 1.0f / cnt;
        float4 mean, stdv;
        mean.x = sum.x * inv; mean.y = sum.y * inv;
        mean.z = sum.z * inv; mean.w = sum.w * inv;
        stdv.x = sqrtf(fmaxf(sum2.x * inv - mean.x * mean.x, 0.f) + 1e-5f);
        stdv.y = sqrtf(fmaxf(sum2.y * inv - mean.y * mean.y, 0.f) + 1e-5f);
        stdv.z = sqrtf(fmaxf(sum2.z * inv - mean.z * mean.z, 0.f) + 1e-5f);
        stdv.w = sqrtf(fmaxf(sum2.w * inv - mean.w * mean.w, 0.f) + 1e-5f);
        float4* sf = (float4*)&g_segfeat[s * 256];
        sf[lane]      = mean;
        sf[16 + lane] = mn;
        sf[32 + lane] = mx;
        sf[48 + lane] = stdv;
    }
}

// ---------------- projection: [S,256] @ Wp[256,64] + bp ----------------
__global__ void k_proj(const float* __restrict__ Wp, const float* __restrict__ bp) {
    int idx = blockIdx.x * blockDim.x + threadIdx.x;
    if (idx >= S_SEG * 64) return;
    int s = idx >> 6, c = idx & 63;
    float acc = bp[c];
    const float* f = &g_segfeat[s * 256];
    #pragma unroll 8
    for (int k = 0; k < 256; k++)
        acc = fmaf(f[k], Wp[k * 64 + c], acc);
    g_proj[idx] = acc;
}

// ---------------- pack: out[b,c,j,i] = proj[offs[b] + i*14+j, c] (masked) ----------------
__global__ void k_pack(const int* __restrict__ num_sp, float* __restrict__ out) {
    int idx = blockIdx.x * blockDim.x + threadIdx.x;
    if (idx >= B_IMG * 64 * 196) return;
    int b   = idx / (64 * 196);
    int rem = idx - b * (64 * 196);
    int c   = rem / 196;
    int ji  = rem - c * 196;
    int j = ji / 14, ii = ji - j * 14;
    int p = ii * 14 + j;
    int ns = num_sp[b];
    int off = 0;
    for (int q = 0; q < b; q++) off += num_sp[q];
    float v = 0.f;
    if (p < ns) {
        int row = off + p;
        if (row > S_SEG - 1) row = S_SEG - 1;
        v = g_proj[row * 64 + c];
    }
    out[idx] = v;
}

// ---------------- host orchestration ----------------
extern "C" void kernel_launch(void* const* d_in, const int* in_sizes, int n_in,
                              void* d_out, int out_size) {
    const float* x        = (const float*)d_in[0];
    const int*   ei       = (const int*)d_in[1];
    const int*   batchidx = (const int*)d_in[2];
    const int*   num_sp   = (const int*)d_in[3];
    const int n = in_sizes[2];
    const int e = in_sizes[1] / 2;
    const int* src = ei;
    const int* dst = ei + e;

    const float* W[5], *g[5], *be[5];
    for (int i = 0; i < 5; i++) {
        W[i]  = (const float*)d_in[4 + 4 * i];
        g[i]  = (const float*)d_in[6 + 4 * i];
        be[i] = (const float*)d_in[7 + 4 * i];
    }
    const float* Wp = (const float*)d_in[24];
    const float* bp = (const float*)d_in[25];
    float* out = (float*)d_out;

    // degrees + CSR build (once per launch)
    k_zero_nodes<<<(n + 255) / 256, 256>>>(n);
    k_deg_count<<<(e + 255) / 256, 256>>>(dst, e);
    int nb = (n + SCAN_CHUNK - 1) / SCAN_CHUNK;
    k_scan1<<<nb, 256>>>(n);
    k_scan2<<<1, 512>>>(nb);
    k_scan3<<<nb, 256>>>(n, e);
    k_fill<<<(e + 255) / 256, 256>>>(src, dst, e);

    const int AB = 1184;   // agg/prep grid
    const int GB = 1184;   // gemm grid

    // L1: GEMM (24->8, writes u=t*dis to B), pure-sum agg B->A (stats slot 0 fused)
    k_gemm2<24, 8, 0><<<GB, 256>>>(x, W[0], n, 0);
    k_agg_tpn<8, false, true><<<AB, 256>>>(n);

    // L2: prep A->B (dim 8, affine from slot 0), agg B->A, gemm 8->16 A->B (slot 1)
    k_prep<8, true><<<AB, 256>>>(n, g[0], be[0], 0);
    k_agg_tpn<8, false, false><<<AB, 256>>>(n);
    k_gemm2<8, 16, 1><<<GB, 256>>>(nullptr, W[1], n, 1);

    // L3: prep B->A (dim 16, slot 1), agg A->B, gemm 16->32 B->A (slot 2)
    k_prep<16, false><<<AB, 256>>>(n, g[1], be[1], 1);
    k_agg_tpn<16, true, false><<<AB, 256>>>(n);
    k_gemm2<16, 32, 2><<<GB, 256>>>(nullptr, W[2], n, 2);

    // L4: prep A->B (dim 32, slot 2), agg B->A, gemm 32->64 A->B (slot 3)
    k_prep<32, true><<<AB, 256>>>(n, g[2], be[2], 2);
    k_agg_grp<32, false><<<AB, 256>>>(n);
    k_gemm2<32, 64, 1><<<GB, 256>>>(nullptr, W[3], n, 3);

    // L5: prep B->A (dim 64, slot 3), agg A->B, gemm 64->64 B->A (slot 4; h5 in A)
    k_prep<64, false><<<AB, 256>>>(n, g[3], be[3], 3);
    k_agg_grp<64, true><<<AB, 256>>>(n);
    k_gemm2<64, 64, 2><<<GB, 256>>>(nullptr, W[4], n, 4);

    // segment aggregation (applies L5 BN affine from slot 4, no ReLU)
    k_segagg<<<S_SEG, 256>>>(batchidx, n, g[4], be[4]);
    k_proj<<<(S_SEG * 64 + 255) / 256, 256>>>(Wp, bp);
    k_pack<<<(B_IMG * 64 * 196 + 255) / 256, 256>>>(num_sp, out);
}

// round 16
// speedup vs baseline: 1.2045x; 1.0399x over previous
#include <cuda_runtime.h>
#include <cuda_fp16.h>
#include <math.h>

// Problem constants (fixed shapes per reference)
#define NN 400000
#define EE 3200000
#define S_SEG 1200
#define B_IMG 8

// ---------------- device scratch (static globals; no allocation) ----------------
__device__ __align__(16) float  g_bufA[(size_t)NN * 64];
__device__ __align__(16) float  g_bufB[(size_t)NN * 64];
__device__ float  g_dis[NN];                 // rsqrt(deg)
__device__ int    g_degi[NN];
__device__ int    g_rowptr[NN + 1];
__device__ int    g_cursor[NN];
__device__ int    g_csr[EE];                 // src indices grouped by dst
__device__ int    g_bsums[512];
__device__ double g_stats[5 * 128];          // per-layer: [slot][sum(64) | sumsq(64)]
__device__ float  g_segfeat[S_SEG * 256];
__device__ float  g_proj[S_SEG * 64];

// ---------------- packed f32x2 helpers (sm_103a) ----------------
__device__ __forceinline__ unsigned long long f2add(unsigned long long a, unsigned long long b) {
    unsigned long long r;
    asm("add.rn.f32x2 %0, %1, %2;" : "=l"(r) : "l"(a), "l"(b));
    return r;
}
__device__ __forceinline__ unsigned long long f2mul(unsigned long long a, unsigned long long b) {
    unsigned long long r;
    asm("mul.rn.f32x2 %0, %1, %2;" : "=l"(r) : "l"(a), "l"(b));
    return r;
}
__device__ __forceinline__ unsigned long long f2pack(float x) {
    unsigned long long r;
    asm("mov.b64 %0, {%1, %1};" : "=l"(r) : "f"(x));
    return r;
}
__device__ __forceinline__ void f2unpack(unsigned long long v, float& lo, float& hi) {
    asm("mov.b64 {%0, %1}, %2;" : "=f"(lo), "=f"(hi) : "l"(v));
}

// BN fold: scale = g*rsqrt(var+eps); shift = be - scale*mean (bias b cancels)
__device__ __forceinline__ void bn_affine(int slot, int c, int n,
                                          const float* gg, const float* bee,
                                          float& sc, float& sh) {
    double s  = g_stats[slot * 128 + c];
    double s2 = g_stats[slot * 128 + 64 + c];
    double mean = s / n;
    double var  = s2 / n - mean * mean;
    float rs = rsqrtf((float)var + 1e-5f);
    sc = gg[c] * rs;
    sh = bee[c] - sc * (float)mean;
}

// ---------------- degree / CSR build ----------------
__global__ void k_zero_nodes(int n) {
    int i = blockIdx.x * blockDim.x + threadIdx.x;
    if (i < n) g_degi[i] = 0;
    if (i < 5 * 128) g_stats[i] = 0.0;
}
__global__ void k_deg_count(const int* __restrict__ dst, int e) {
    int i = blockIdx.x * blockDim.x + threadIdx.x;
    if (i < e) atomicAdd(&g_degi[dst[i]], 1);
}

#define SCAN_CHUNK 1024
// scan of degi -> rowptr (block-local) + dis = rsqrt(deg+1) fused
__global__ void k_scan1(int n) {
    __shared__ int sh[256];
    int base = blockIdx.x * SCAN_CHUNK;
    int t = threadIdx.x;
    int v[4]; int loc = 0;
    #pragma unroll
    for (int k = 0; k < 4; k++) {
        int i = base + t * 4 + k;
        v[k] = (i < n) ? g_degi[i] : 0;
        if (i < n) g_dis[i] = rsqrtf((float)(v[k] + 1));
        loc += v[k];
    }
    sh[t] = loc;
    __syncthreads();
    for (int off = 1; off < 256; off <<= 1) {
        int x = sh[t];
        int y = (t >= off) ? sh[t - off] : 0;
        __syncthreads();
        sh[t] = x + y;
        __syncthreads();
    }
    int excl = (t == 0) ? 0 : sh[t - 1];
    if (t == 255) g_bsums[blockIdx.x] = sh[255];
    int run = excl;
    #pragma unroll
    for (int k = 0; k < 4; k++) {
        int i = base + t * 4 + k;
        if (i < n) g_rowptr[i] = run;
        run += v[k];
    }
}
__global__ void k_scan2(int nb) {
    __shared__ int sh[512];
    int t = threadIdx.x;
    sh[t] = (t < nb) ? g_bsums[t] : 0;
    __syncthreads();
    for (int off = 1; off < 512; off <<= 1) {
        int x = sh[t];
        int y = (t >= off) ? sh[t - off] : 0;
        __syncthreads();
        sh[t] = x + y;
        __syncthreads();
    }
    if (t < nb) g_bsums[t] = (t == 0) ? 0 : sh[t - 1];
}
// finalize rowptr; also copy into cursor so k_fill's atomicAdd yields absolute slots
__global__ void k_scan3(int n, int e) {
    int base = blockIdx.x * SCAN_CHUNK;
    int add = g_bsums[blockIdx.x];
    int t = threadIdx.x;
    #pragma unroll
    for (int k = 0; k < 4; k++) {
        int i = base + t * 4 + k;
        if (i < n) {
            int r = g_rowptr[i] + add;
            g_rowptr[i] = r;
            g_cursor[i] = r;
        }
    }
    if (blockIdx.x == 0 && t == 0) g_rowptr[n] = e;
}
__global__ void k_fill(const int* __restrict__ src, const int* __restrict__ dst, int e) {
    int i = blockIdx.x * blockDim.x + threadIdx.x;
    if (i < e) {
        int p = atomicAdd(&g_cursor[dst[i]], 1);
        g_csr[p] = src[i];
    }
}

// ---------------- prep: u = relu(affine(h)) * dis  (streaming; affine from stats slot) ----------------
template<int D, bool IN_A>
__global__ void k_prep(int n, const float* __restrict__ gg, const float* __restrict__ bee,
                       int slot) {
    constexpr int NC = D / 4;
    __shared__ __align__(16) float sc_s[D], sh_s[D];
    int t = threadIdx.x;
    if (t < D) {
        float sc, sh;
        bn_affine(slot, t, n, gg, bee, sc, sh);
        sc_s[t] = sc; sh_s[t] = sh;
    }
    __syncthreads();
    const float4* in = (const float4*)(IN_A ? g_bufA : g_bufB);
    float4* out      = (float4*)(IN_A ? g_bufB : g_bufA);
    const float4* sc4 = (const float4*)sc_s;
    const float4* sh4 = (const float4*)sh_s;
    long long tot = (long long)n * NC;
    for (long long idx = (long long)blockIdx.x * blockDim.x + threadIdx.x;
         idx < tot; idx += (long long)gridDim.x * blockDim.x) {
        int node = (int)(idx / NC);
        int f = (int)(idx - (long long)node * NC);
        float dd = g_dis[node];
        float4 sc = sc4[f];
        float4 sh = sh4[f];
        float4 v = in[idx];
        float4 o;
        o.x = fmaxf(fmaf(sc.x, v.x, sh.x), 0.f) * dd;
        o.y = fmaxf(fmaf(sc.y, v.y, sh.y), 0.f) * dd;
        o.z = fmaxf(fmaf(sc.z, v.z, sh.z), 0.f) * dd;
        o.w = fmaxf(fmaf(sc.w, v.w, sh.w), 0.f) * dd;
        out[idx] = o;
    }
}

// ---------------- L5 prep (fp16 output): u5 = half(relu(affine(h4))*dis), B -> A ----------------
__global__ void k_prep64h(int n, const float* __restrict__ gg, const float* __restrict__ bee,
                          int slot) {
    __shared__ __align__(16) float sc_s[64], sh_s[64];
    int t = threadIdx.x;
    if (t < 64) {
        float sc, sh;
        bn_affine(slot, t, n, gg, bee, sc, sh);
        sc_s[t] = sc; sh_s[t] = sh;
    }
    __syncthreads();
    const float4* in = (const float4*)g_bufB;   // h4 fp32, 16 float4 per node
    uint2* out = (uint2*)g_bufA;                // u5 fp16, 16 uint2 per node
    const float4* sc4 = (const float4*)sc_s;
    const float4* sh4 = (const float4*)sh_s;
    long long tot = (long long)n * 16;
    for (long long idx = (long long)blockIdx.x * blockDim.x + threadIdx.x;
         idx < tot; idx += (long long)gridDim.x * blockDim.x) {
        int node = (int)(idx >> 4);
        int f = (int)(idx & 15);
        float dd = g_dis[node];
        float4 sc = sc4[f];
        float4 sh = sh4[f];
        float4 v = in[idx];
        float o0 = fmaxf(fmaf(sc.x, v.x, sh.x), 0.f) * dd;
        float o1 = fmaxf(fmaf(sc.y, v.y, sh.y), 0.f) * dd;
        float o2 = fmaxf(fmaf(sc.z, v.z, sh.z), 0.f) * dd;
        float o3 = fmaxf(fmaf(sc.w, v.w, sh.w), 0.f) * dd;
        __half2 h0 = __float22half2_rn(make_float2(o0, o1));
        __half2 h1 = __float22half2_rn(make_float2(o2, o3));
        uint2 packed;
        packed.x = *(unsigned int*)&h0;
        packed.y = *(unsigned int*)&h1;
        out[idx] = packed;
    }
}

// ---------------- L5 gather (u fp16 in A, fp32 accumulate, z fp32 -> B) ----------------
__global__ void k_agg64h(int n) {
    constexpr int TPN = 16;          // lanes per node; 8B (4 half channels) each
    constexpr int NPB = 256 / TPN;
    int tid = threadIdx.x;
    int grp = tid / TPN, lane = tid % TPN;
    const uint2* in = (const uint2*)g_bufA;
    float4* out = (float4*)g_bufB;
    for (int d = blockIdx.x * NPB + grp; d < n; d += gridDim.x * NPB) {
        uint2 sv = in[(size_t)d * TPN + lane];   // self term
        float2 a0 = __half22float2(*(__half2*)&sv.x);
        float2 a1 = __half22float2(*(__half2*)&sv.y);
        float4 acc = make_float4(a0.x, a0.y, a1.x, a1.y);
        int beg = g_rowptr[d], end = g_rowptr[d + 1];
        #pragma unroll 4
        for (int j = beg; j < end; j++) {
            int s = g_csr[j];
            uint2 v = in[(size_t)s * TPN + lane];
            float2 f0 = __half22float2(*(__half2*)&v.x);
            float2 f1 = __half22float2(*(__half2*)&v.y);
            acc.x += f0.x; acc.y += f0.y;
            acc.z += f1.x; acc.w += f1.y;
        }
        float dd = g_dis[d];
        acc.x *= dd; acc.y *= dd; acc.z *= dd; acc.w *= dd;
        out[(size_t)d * TPN + lane] = acc;
    }
}

// ---------------- pure-sum gather, thread-per-node (D=8/16), packed adds ----------------
template<int D, bool IN_A, bool STATS>
__global__ void k_agg_tpn(int n) {
    constexpr int NC = D / 4;   // 16B chunks per node
    __shared__ float ss[8], ss2[8];
    int tid = threadIdx.x;
    if (STATS) {
        if (tid < 8) { ss[tid] = 0.f; ss2[tid] = 0.f; }
        __syncthreads();
    }
    const ulonglong2* in = (const ulonglong2*)(IN_A ? g_bufA : g_bufB);
    ulonglong2* out      = (ulonglong2*)(IN_A ? g_bufB : g_bufA);
    float ls[8], ls2[8];
    if (STATS) {
        #pragma unroll
        for (int c = 0; c < 8; c++) { ls[c] = 0.f; ls2[c] = 0.f; }
    }
    for (int d = blockIdx.x * blockDim.x + threadIdx.x; d < n; d += gridDim.x * blockDim.x) {
        ulonglong2 acc[NC];
        #pragma unroll
        for (int f = 0; f < NC; f++) acc[f] = in[(size_t)d * NC + f];   // self term u[d]
        int beg = g_rowptr[d], end = g_rowptr[d + 1];
        #pragma unroll 2
        for (int j = beg; j < end; j++) {
            int s = g_csr[j];
            #pragma unroll
            for (int f = 0; f < NC; f++) {
                ulonglong2 v = in[(size_t)s * NC + f];
                acc[f].x = f2add(acc[f].x, v.x);
                acc[f].y = f2add(acc[f].y, v.y);
            }
        }
        unsigned long long dd2 = f2pack(g_dis[d]);
        #pragma unroll
        for (int f = 0; f < NC; f++) {
            acc[f].x = f2mul(acc[f].x, dd2);
            acc[f].y = f2mul(acc[f].y, dd2);
            out[(size_t)d * NC + f] = acc[f];
            if (STATS) {
                float a, b;
                f2unpack(acc[f].x, a, b);
                ls[f * 4 + 0] += a; ls2[f * 4 + 0] += a * a;
                ls[f * 4 + 1] += b; ls2[f * 4 + 1] += b * b;
                f2unpack(acc[f].y, a, b);
                ls[f * 4 + 2] += a; ls2[f * 4 + 2] += a * a;
                ls[f * 4 + 3] += b; ls2[f * 4 + 3] += b * b;
            }
        }
    }
    if (STATS) {
        #pragma unroll
        for (int c = 0; c < 8; c++) {
            atomicAdd(&ss[c], ls[c]);
            atomicAdd(&ss2[c], ls2[c]);
        }
        __syncthreads();
        if (tid < 8) {
            atomicAdd(&g_stats[tid], (double)ss[tid]);          // slot 0
            atomicAdd(&g_stats[64 + tid], (double)ss2[tid]);
        }
    }
}

// ---------------- pure-sum gather, group variant (D=32), packed adds ----------------
template<int D, bool IN_A>
__global__ void k_agg_grp(int n) {
    constexpr int TPN = D / 4;          // lanes per node (16B each)
    constexpr int NPB = 256 / TPN;
    int tid = threadIdx.x;
    int grp = tid / TPN, lane = tid % TPN;
    const ulonglong2* in = (const ulonglong2*)(IN_A ? g_bufA : g_bufB);
    ulonglong2* out      = (ulonglong2*)(IN_A ? g_bufB : g_bufA);
    for (int d = blockIdx.x * NPB + grp; d < n; d += gridDim.x * NPB) {
        ulonglong2 acc = in[(size_t)d * TPN + lane];   // self term
        int beg = g_rowptr[d], end = g_rowptr[d + 1];
        #pragma unroll 4
        for (int j = beg; j < end; j++) {
            int s = g_csr[j];
            ulonglong2 v = in[(size_t)s * TPN + lane];
            acc.x = f2add(acc.x, v.x);
            acc.y = f2add(acc.y, v.y);
        }
        unsigned long long dd2 = f2pack(g_dis[d]);
        acc.x = f2mul(acc.x, dd2);
        acc.y = f2mul(acc.y, dd2);
        out[(size_t)d * TPN + lane] = acc;
    }
}

// ---------------- GEMM, 32-node tiles, W in registers ----------------
// MODE 0: xin -> bufB, epilogue *dis[node], no stats (layer 1)
// MODE 1: bufA -> bufB, fused BN stats -> slot
// MODE 2: bufB -> bufA, fused BN stats -> slot
template<int FI, int FO, int MODE>
__global__ void k_gemm2(const float* __restrict__ xin, const float* __restrict__ W,
                        int n, int slot) {
    constexpr int TILE = 32;
    constexpr int NPB = 256 / FO;        // node-slots worked concurrently
    constexpr int NPT = TILE / NPB;      // nodes per thread per tile
    __shared__ float xs[TILE * FI];
    const float* zin = (MODE == 0) ? xin : (MODE == 1 ? g_bufA : g_bufB);
    float* hout      = (MODE == 0) ? g_bufB : (MODE == 1 ? g_bufB : g_bufA);
    int tid = threadIdx.x;
    int c = tid % FO, grp = tid / FO;
    float w[FI];
    #pragma unroll
    for (int k = 0; k < FI; k++) w[k] = W[k * FO + c];
    float s1 = 0.f, s2 = 0.f;
    int ntiles = (n + TILE - 1) / TILE;
    constexpr int NV = TILE * FI / 4;
    for (int t = blockIdx.x; t < ntiles; t += gridDim.x) {
        int base = t * TILE;
        __syncthreads();
        const float4* src4 = (const float4*)(zin + (size_t)base * FI);
        float4* xs4 = (float4*)xs;
        if (base + TILE <= n) {
            #pragma unroll
            for (int i = tid; i < NV; i += 256) xs4[i] = src4[i];
        } else {
            for (int i = tid; i < NV; i += 256) {
                int node = base + (i * 4) / FI;
                xs4[i] = (node < n) ? src4[i] : make_float4(0.f, 0.f, 0.f, 0.f);
            }
        }
        __syncthreads();
        #pragma unroll
        for (int u = 0; u < NPT; u++) {
            int slotn = grp + u * NPB;
            int node = base + slotn;
            if (node < n) {
                float acc = 0.f;
                const float4* row = (const float4*)(xs + slotn * FI);
                #pragma unroll
                for (int k4 = 0; k4 < FI / 4; k4++) {
                    float4 z4 = row[k4];
                    acc = fmaf(z4.x, w[k4 * 4 + 0], acc);
                    acc = fmaf(z4.y, w[k4 * 4 + 1], acc);
                    acc = fmaf(z4.z, w[k4 * 4 + 2], acc);
                    acc = fmaf(z4.w, w[k4 * 4 + 3], acc);
                }
                if (MODE == 0) {
                    hout[(size_t)node * FO + c] = acc * g_dis[node];
                } else {
                    hout[(size_t)node * FO + c] = acc;
                    s1 += acc; s2 += acc * acc;
                }
            }
        }
    }
    if (MODE != 0) {
        __shared__ float r1[256], r2[256];
        r1[tid] = s1; r2[tid] = s2;
        __syncthreads();
        if (tid < FO) {
            float a = 0.f, b = 0.f;
            #pragma unroll
            for (int k = 0; k < NPB; k++) { a += r1[k * FO + tid]; b += r2[k * FO + tid]; }
            atomicAdd(&g_stats[slot * 128 + tid], (double)a);
            atomicAdd(&g_stats[slot * 128 + 64 + tid], (double)b);
        }
    }
}

// ---------------- segment multi-aggregation (batch_idx sorted, coalesced float4) ----------------
// Applies layer-5 BN affine computed in-block from stats slot 4.
__global__ void k_segagg(const int* __restrict__ bidx, int n,
                         const float* __restrict__ gg, const float* __restrict__ bee) {
    int s = blockIdx.x;
    int tid = threadIdx.x;
    int lane = tid & 15;    // float4 channel chunk
    int rowg = tid >> 4;    // 0..15
    __shared__ int se[2];
    __shared__ __align__(16) float sc_s[64], sh_s[64];
    if (tid < 2) {
        int target = s + tid;
        int lo = 0, hi = n;
        while (lo < hi) { int m = (lo + hi) >> 1; if (bidx[m] < target) lo = m + 1; else hi = m; }
        se[tid] = lo;
    }
    if (tid < 64) {
        float sc, sh;
        bn_affine(4, tid, n, gg, bee, sc, sh);
        sc_s[tid] = sc; sh_s[tid] = sh;
    }
    __syncthreads();
    int start = se[0], end = se[1];
    float4 sc = ((const float4*)sc_s)[lane];
    float4 sh = ((const float4*)sh_s)[lane];
    float4 sum = make_float4(0.f, 0.f, 0.f, 0.f);
    float4 sum2 = make_float4(0.f, 0.f, 0.f, 0.f);
    float4 mn = make_float4(INFINITY, INFINITY, INFINITY, INFINITY);
    float4 mx = make_float4(-INFINITY, -INFINITY, -INFINITY, -INFINITY);
    const float4* in = (const float4*)g_bufA;
    for (int r = start + rowg; r < end; r += 16) {
        float4 v = in[(size_t)r * 16 + lane];
        float a0 = fmaf(sc.x, v.x, sh.x);
        float a1 = fmaf(sc.y, v.y, sh.y);
        float a2 = fmaf(sc.z, v.z, sh.z);
        float a3 = fmaf(sc.w, v.w, sh.w);
        sum.x += a0; sum2.x += a0 * a0; mn.x = fminf(mn.x, a0); mx.x = fmaxf(mx.x, a0);
        sum.y += a1; sum2.y += a1 * a1; mn.y = fminf(mn.y, a1); mx.y = fmaxf(mx.y, a1);
        sum.z += a2; sum2.z += a2 * a2; mn.z = fminf(mn.z, a2); mx.z = fmaxf(mx.z, a2);
        sum.w += a3; sum2.w += a3 * a3; mn.w = fminf(mn.w, a3); mx.w = fmaxf(mx.w, a3);
    }
    __shared__ float4 rs1[256], rs2[256], rmn[256], rmx[256];
    rs1[tid] = sum; rs2[tid] = sum2; rmn[tid] = mn; rmx[tid] = mx;
    __syncthreads();
    if (rowg == 0) {
        #pragma unroll
        for (int k = 1; k < 16; k++) {
            float4 a = rs1[k * 16 + lane], b = rs2[k * 16 + lane];
            float4 c = rmn[k * 16 + lane], d = rmx[k * 16 + lane];
            sum.x += a.x; sum.y += a.y; sum.z += a.z; sum.w += a.w;
            sum2.x += b.x; sum2.y += b.y; sum2.z += b.z; sum2.w += b.w;
            mn.x = fminf(mn.x, c.x); mn.y = fminf(mn.y, c.y);
            mn.z = fminf(mn.z, c.z); mn.w = fminf(mn.w, c.w);
            mx.x = fmaxf(mx.x, d.x); mx.y = fmaxf(mx.y, d.y);
            mx.z = fmaxf(mx.z, d.z); mx.w = fmaxf(mx.w, d.w);
        }
        float cnt = fmaxf((float)(end - start), 1.0f);
        float inv = 1.0f / cnt;
        float4 mean, stdv;
        mean.x = sum.x * inv; mean.y = sum.y * inv;
        mean.z = sum.z * inv; mean.w = sum.w * inv;
        stdv.x = sqrtf(fmaxf(sum2.x * inv - mean.x * mean.x, 0.f) + 1e-5f);
        stdv.y = sqrtf(fmaxf(sum2.y * inv - mean.y * mean.y, 0.f) + 1e-5f);
        stdv.z = sqrtf(fmaxf(sum2.z * inv - mean.z * mean.z, 0.f) + 1e-5f);
        stdv.w = sqrtf(fmaxf(sum2.w * inv - mean.w * mean.w, 0.f) + 1e-5f);
        float4* sf = (float4*)&g_segfeat[s * 256];
        sf[lane]      = mean;
        sf[16 + lane] = mn;
        sf[32 + lane] = mx;
        sf[48 + lane] = stdv;
    }
}

// ---------------- projection: [S,256] @ Wp[256,64] + bp ----------------
__global__ void k_proj(const float* __restrict__ Wp, const float* __restrict__ bp) {
    int idx = blockIdx.x * blockDim.x + threadIdx.x;
    if (idx >= S_SEG * 64) return;
    int s = idx >> 6, c = idx & 63;
    float acc = bp[c];
    const float* f = &g_segfeat[s * 256];
    #pragma unroll 8
    for (int k = 0; k < 256; k++)
        acc = fmaf(f[k], Wp[k * 64 + c], acc);
    g_proj[idx] = acc;
}

// ---------------- pack: out[b,c,j,i] = proj[offs[b] + i*14+j, c] (masked) ----------------
__global__ void k_pack(const int* __restrict__ num_sp, float* __restrict__ out) {
    int idx = blockIdx.x * blockDim.x + threadIdx.x;
    if (idx >= B_IMG * 64 * 196) return;
    int b   = idx / (64 * 196);
    int rem = idx - b * (64 * 196);
    int c   = rem / 196;
    int ji  = rem - c * 196;
    int j = ji / 14, ii = ji - j * 14;
    int p = ii * 14 + j;
    int ns = num_sp[b];
    int off = 0;
    for (int q = 0; q < b; q++) off += num_sp[q];
    float v = 0.f;
    if (p < ns) {
        int row = off + p;
        if (row > S_SEG - 1) row = S_SEG - 1;
        v = g_proj[row * 64 + c];
    }
    out[idx] = v;
}

// ---------------- host orchestration ----------------
extern "C" void kernel_launch(void* const* d_in, const int* in_sizes, int n_in,
                              void* d_out, int out_size) {
    const float* x        = (const float*)d_in[0];
    const int*   ei       = (const int*)d_in[1];
    const int*   batchidx = (const int*)d_in[2];
    const int*   num_sp   = (const int*)d_in[3];
    const int n = in_sizes[2];
    const int e = in_sizes[1] / 2;
    const int* src = ei;
    const int* dst = ei + e;

    const float* W[5], *g[5], *be[5];
    for (int i = 0; i < 5; i++) {
        W[i]  = (const float*)d_in[4 + 4 * i];
        g[i]  = (const float*)d_in[6 + 4 * i];
        be[i] = (const float*)d_in[7 + 4 * i];
    }
    const float* Wp = (const float*)d_in[24];
    const float* bp = (const float*)d_in[25];
    float* out = (float*)d_out;

    // degrees + CSR build (once per launch)
    k_zero_nodes<<<(n + 255) / 256, 256>>>(n);
    k_deg_count<<<(e + 255) / 256, 256>>>(dst, e);
    int nb = (n + SCAN_CHUNK - 1) / SCAN_CHUNK;
    k_scan1<<<nb, 256>>>(n);
    k_scan2<<<1, 512>>>(nb);
    k_scan3<<<nb, 256>>>(n, e);
    k_fill<<<(e + 255) / 256, 256>>>(src, dst, e);

    const int AB = 1184;   // agg/prep grid
    const int GB = 1184;   // gemm grid

    // L1: GEMM (24->8, writes u=t*dis to B), pure-sum agg B->A (stats slot 0 fused)
    k_gemm2<24, 8, 0><<<GB, 256>>>(x, W[0], n, 0);
    k_agg_tpn<8, false, true><<<AB, 256>>>(n);

    // L2: prep A->B (dim 8, affine from slot 0), agg B->A, gemm 8->16 A->B (slot 1)
    k_prep<8, true><<<AB, 256>>>(n, g[0], be[0], 0);
    k_agg_tpn<8, false, false><<<AB, 256>>>(n);
    k_gemm2<8, 16, 1><<<GB, 256>>>(nullptr, W[1], n, 1);

    // L3: prep B->A (dim 16, slot 1), agg A->B, gemm 16->32 B->A (slot 2)
    k_prep<16, false><<<AB, 256>>>(n, g[1], be[1], 1);
    k_agg_tpn<16, true, false><<<AB, 256>>>(n);
    k_gemm2<16, 32, 2><<<GB, 256>>>(nullptr, W[2], n, 2);

    // L4: prep A->B (dim 32, slot 2), agg B->A, gemm 32->64 A->B (slot 3)
    k_prep<32, true><<<AB, 256>>>(n, g[2], be[2], 2);
    k_agg_grp<32, false><<<AB, 256>>>(n);
    k_gemm2<32, 64, 1><<<GB, 256>>>(nullptr, W[3], n, 3);

    // L5: prep B->A fp16 (dim 64, slot 3), fp16 gather A->B, gemm 64->64 B->A (slot 4; h5 in A)
    k_prep64h<<<AB, 256>>>(n, g[3], be[3], 3);
    k_agg64h<<<AB, 256>>>(n);
    k_gemm2<64, 64, 2><<<GB, 256>>>(nullptr, W[4], n, 4);

    // segment aggregation (applies L5 BN affine from slot 4, no ReLU)
    k_segagg<<<S_SEG, 256>>>(batchidx, n, g[4], be[4]);
    k_proj<<<(S_SEG * 64 + 255) / 256, 256>>>(Wp, bp);
    k_pack<<<(B_IMG * 64 * 196 + 255) / 256, 256>>>(num_sp, out);
}

// round 17
// speedup vs baseline: 1.2172x; 1.0106x over previous
#include <cuda_runtime.h>
#include <cuda_fp16.h>
#include <math.h>

// Problem constants (fixed shapes per reference)
#define NN 400000
#define EE 3200000
#define S_SEG 1200
#define B_IMG 8

// ---------------- device scratch (static globals; no allocation) ----------------
__device__ __align__(16) float  g_bufA[(size_t)NN * 64];
__device__ __align__(16) float  g_bufB[(size_t)NN * 64];
__device__ float  g_dis[NN];                 // rsqrt(deg)
__device__ int    g_degi[NN];
__device__ int    g_rowptr[NN + 1];
__device__ int    g_cursor[NN];
__device__ int    g_csr[EE];                 // src indices grouped by dst
__device__ int    g_bsums[512];
__device__ double g_stats[5 * 128];          // per-layer: [slot][sum(64) | sumsq(64)]
__device__ float  g_segfeat[S_SEG * 256];
__device__ float  g_proj[S_SEG * 64];

// ---------------- packed f32x2 helpers (sm_103a) ----------------
__device__ __forceinline__ unsigned long long f2add(unsigned long long a, unsigned long long b) {
    unsigned long long r;
    asm("add.rn.f32x2 %0, %1, %2;" : "=l"(r) : "l"(a), "l"(b));
    return r;
}
__device__ __forceinline__ unsigned long long f2mul(unsigned long long a, unsigned long long b) {
    unsigned long long r;
    asm("mul.rn.f32x2 %0, %1, %2;" : "=l"(r) : "l"(a), "l"(b));
    return r;
}
__device__ __forceinline__ unsigned long long f2pack(float x) {
    unsigned long long r;
    asm("mov.b64 %0, {%1, %1};" : "=l"(r) : "f"(x));
    return r;
}
__device__ __forceinline__ void f2unpack(unsigned long long v, float& lo, float& hi) {
    asm("mov.b64 {%0, %1}, %2;" : "=f"(lo), "=f"(hi) : "l"(v));
}

// BN fold: scale = g*rsqrt(var+eps); shift = be - scale*mean (bias b cancels)
__device__ __forceinline__ void bn_affine(int slot, int c, int n,
                                          const float* gg, const float* bee,
                                          float& sc, float& sh) {
    double s  = g_stats[slot * 128 + c];
    double s2 = g_stats[slot * 128 + 64 + c];
    double mean = s / n;
    double var  = s2 / n - mean * mean;
    float rs = rsqrtf((float)var + 1e-5f);
    sc = gg[c] * rs;
    sh = bee[c] - sc * (float)mean;
}

// ---------------- degree / CSR build ----------------
__global__ void k_zero_nodes(int n) {
    int i = blockIdx.x * blockDim.x + threadIdx.x;
    if (i < n) g_degi[i] = 0;
    if (i < 5 * 128) g_stats[i] = 0.0;
}
__global__ void k_deg_count(const int* __restrict__ dst, int e) {
    int i = blockIdx.x * blockDim.x + threadIdx.x;
    if (i < e) atomicAdd(&g_degi[dst[i]], 1);
}

#define SCAN_CHUNK 1024
// scan of degi -> rowptr (block-local) + dis = rsqrt(deg+1) fused
__global__ void k_scan1(int n) {
    __shared__ int sh[256];
    int base = blockIdx.x * SCAN_CHUNK;
    int t = threadIdx.x;
    int v[4]; int loc = 0;
    #pragma unroll
    for (int k = 0; k < 4; k++) {
        int i = base + t * 4 + k;
        v[k] = (i < n) ? g_degi[i] : 0;
        if (i < n) g_dis[i] = rsqrtf((float)(v[k] + 1));
        loc += v[k];
    }
    sh[t] = loc;
    __syncthreads();
    for (int off = 1; off < 256; off <<= 1) {
        int x = sh[t];
        int y = (t >= off) ? sh[t - off] : 0;
        __syncthreads();
        sh[t] = x + y;
        __syncthreads();
    }
    int excl = (t == 0) ? 0 : sh[t - 1];
    if (t == 255) g_bsums[blockIdx.x] = sh[255];
    int run = excl;
    #pragma unroll
    for (int k = 0; k < 4; k++) {
        int i = base + t * 4 + k;
        if (i < n) g_rowptr[i] = run;
        run += v[k];
    }
}
__global__ void k_scan2(int nb) {
    __shared__ int sh[512];
    int t = threadIdx.x;
    sh[t] = (t < nb) ? g_bsums[t] : 0;
    __syncthreads();
    for (int off = 1; off < 512; off <<= 1) {
        int x = sh[t];
        int y = (t >= off) ? sh[t - off] : 0;
        __syncthreads();
        sh[t] = x + y;
        __syncthreads();
    }
    if (t < nb) g_bsums[t] = (t == 0) ? 0 : sh[t - 1];
}
// finalize rowptr; also copy into cursor so k_fill's atomicAdd yields absolute slots
__global__ void k_scan3(int n, int e) {
    int base = blockIdx.x * SCAN_CHUNK;
    int add = g_bsums[blockIdx.x];
    int t = threadIdx.x;
    #pragma unroll
    for (int k = 0; k < 4; k++) {
        int i = base + t * 4 + k;
        if (i < n) {
            int r = g_rowptr[i] + add;
            g_rowptr[i] = r;
            g_cursor[i] = r;
        }
    }
    if (blockIdx.x == 0 && t == 0) g_rowptr[n] = e;
}
__global__ void k_fill(const int* __restrict__ src, const int* __restrict__ dst, int e) {
    int i = blockIdx.x * blockDim.x + threadIdx.x;
    if (i < e) {
        int p = atomicAdd(&g_cursor[dst[i]], 1);
        g_csr[p] = src[i];
    }
}

// ---------------- prep: u = relu(affine(h)) * dis  (fp32 out; affine from stats slot) ----------------
template<int D, bool IN_A>
__global__ void k_prep(int n, const float* __restrict__ gg, const float* __restrict__ bee,
                       int slot) {
    constexpr int NC = D / 4;
    __shared__ __align__(16) float sc_s[D], sh_s[D];
    int t = threadIdx.x;
    if (t < D) {
        float sc, sh;
        bn_affine(slot, t, n, gg, bee, sc, sh);
        sc_s[t] = sc; sh_s[t] = sh;
    }
    __syncthreads();
    const float4* in = (const float4*)(IN_A ? g_bufA : g_bufB);
    float4* out      = (float4*)(IN_A ? g_bufB : g_bufA);
    const float4* sc4 = (const float4*)sc_s;
    const float4* sh4 = (const float4*)sh_s;
    long long tot = (long long)n * NC;
    for (long long idx = (long long)blockIdx.x * blockDim.x + threadIdx.x;
         idx < tot; idx += (long long)gridDim.x * blockDim.x) {
        int node = (int)(idx / NC);
        int f = (int)(idx - (long long)node * NC);
        float dd = g_dis[node];
        float4 sc = sc4[f];
        float4 sh = sh4[f];
        float4 v = in[idx];
        float4 o;
        o.x = fmaxf(fmaf(sc.x, v.x, sh.x), 0.f) * dd;
        o.y = fmaxf(fmaf(sc.y, v.y, sh.y), 0.f) * dd;
        o.z = fmaxf(fmaf(sc.z, v.z, sh.z), 0.f) * dd;
        o.w = fmaxf(fmaf(sc.w, v.w, sh.w), 0.f) * dd;
        out[idx] = o;
    }
}

// ---------------- fp16 prep: u = half(relu(affine(h))*dis)  (D = 32 or 64) ----------------
template<int D, bool IN_A>
__global__ void k_preph(int n, const float* __restrict__ gg, const float* __restrict__ bee,
                        int slot) {
    constexpr int NC = D / 4;   // 4-channel chunks per node
    __shared__ __align__(16) float sc_s[D], sh_s[D];
    int t = threadIdx.x;
    if (t < D) {
        float sc, sh;
        bn_affine(slot, t, n, gg, bee, sc, sh);
        sc_s[t] = sc; sh_s[t] = sh;
    }
    __syncthreads();
    const float4* in = (const float4*)(IN_A ? g_bufA : g_bufB);   // h fp32
    uint2* out = (uint2*)(IN_A ? g_bufB : g_bufA);                // u fp16
    const float4* sc4 = (const float4*)sc_s;
    const float4* sh4 = (const float4*)sh_s;
    long long tot = (long long)n * NC;
    for (long long idx = (long long)blockIdx.x * blockDim.x + threadIdx.x;
         idx < tot; idx += (long long)gridDim.x * blockDim.x) {
        int node = (int)(idx / NC);
        int f = (int)(idx - (long long)node * NC);
        float dd = g_dis[node];
        float4 sc = sc4[f];
        float4 sh = sh4[f];
        float4 v = in[idx];
        float o0 = fmaxf(fmaf(sc.x, v.x, sh.x), 0.f) * dd;
        float o1 = fmaxf(fmaf(sc.y, v.y, sh.y), 0.f) * dd;
        float o2 = fmaxf(fmaf(sc.z, v.z, sh.z), 0.f) * dd;
        float o3 = fmaxf(fmaf(sc.w, v.w, sh.w), 0.f) * dd;
        __half2 h0 = __float22half2_rn(make_float2(o0, o1));
        __half2 h1 = __float22half2_rn(make_float2(o2, o3));
        uint2 packed;
        packed.x = *(unsigned int*)&h0;
        packed.y = *(unsigned int*)&h1;
        out[idx] = packed;
    }
}

// ---------------- fp16 gather (u fp16, fp32 accumulate, z fp32) (D = 32 or 64) ----------------
template<int D, bool IN_A>
__global__ void k_aggh(int n) {
    constexpr int TPN = D / 4;       // lanes per node; 8B (4 half channels) each
    constexpr int NPB = 256 / TPN;
    int tid = threadIdx.x;
    int grp = tid / TPN, lane = tid % TPN;
    const uint2* in = (const uint2*)(IN_A ? g_bufA : g_bufB);
    float4* out = (float4*)(IN_A ? g_bufB : g_bufA);
    for (int d = blockIdx.x * NPB + grp; d < n; d += gridDim.x * NPB) {
        uint2 sv = in[(size_t)d * TPN + lane];   // self term
        float2 a0 = __half22float2(*(__half2*)&sv.x);
        float2 a1 = __half22float2(*(__half2*)&sv.y);
        float4 acc = make_float4(a0.x, a0.y, a1.x, a1.y);
        int beg = g_rowptr[d], end = g_rowptr[d + 1];
        #pragma unroll 4
        for (int j = beg; j < end; j++) {
            int s = g_csr[j];
            uint2 v = in[(size_t)s * TPN + lane];
            float2 f0 = __half22float2(*(__half2*)&v.x);
            float2 f1 = __half22float2(*(__half2*)&v.y);
            acc.x += f0.x; acc.y += f0.y;
            acc.z += f1.x; acc.w += f1.y;
        }
        float dd = g_dis[d];
        acc.x *= dd; acc.y *= dd; acc.z *= dd; acc.w *= dd;
        out[(size_t)d * TPN + lane] = acc;
    }
}

// ---------------- pure-sum gather, thread-per-node (D=8/16), packed adds ----------------
template<int D, bool IN_A, bool STATS>
__global__ void k_agg_tpn(int n) {
    constexpr int NC = D / 4;   // 16B chunks per node
    __shared__ float ss[8], ss2[8];
    int tid = threadIdx.x;
    if (STATS) {
        if (tid < 8) { ss[tid] = 0.f; ss2[tid] = 0.f; }
        __syncthreads();
    }
    const ulonglong2* in = (const ulonglong2*)(IN_A ? g_bufA : g_bufB);
    ulonglong2* out      = (ulonglong2*)(IN_A ? g_bufB : g_bufA);
    float ls[8], ls2[8];
    if (STATS) {
        #pragma unroll
        for (int c = 0; c < 8; c++) { ls[c] = 0.f; ls2[c] = 0.f; }
    }
    for (int d = blockIdx.x * blockDim.x + threadIdx.x; d < n; d += gridDim.x * blockDim.x) {
        ulonglong2 acc[NC];
        #pragma unroll
        for (int f = 0; f < NC; f++) acc[f] = in[(size_t)d * NC + f];   // self term u[d]
        int beg = g_rowptr[d], end = g_rowptr[d + 1];
        #pragma unroll 2
        for (int j = beg; j < end; j++) {
            int s = g_csr[j];
            #pragma unroll
            for (int f = 0; f < NC; f++) {
                ulonglong2 v = in[(size_t)s * NC + f];
                acc[f].x = f2add(acc[f].x, v.x);
                acc[f].y = f2add(acc[f].y, v.y);
            }
        }
        unsigned long long dd2 = f2pack(g_dis[d]);
        #pragma unroll
        for (int f = 0; f < NC; f++) {
            acc[f].x = f2mul(acc[f].x, dd2);
            acc[f].y = f2mul(acc[f].y, dd2);
            out[(size_t)d * NC + f] = acc[f];
            if (STATS) {
                float a, b;
                f2unpack(acc[f].x, a, b);
                ls[f * 4 + 0] += a; ls2[f * 4 + 0] += a * a;
                ls[f * 4 + 1] += b; ls2[f * 4 + 1] += b * b;
                f2unpack(acc[f].y, a, b);
                ls[f * 4 + 2] += a; ls2[f * 4 + 2] += a * a;
                ls[f * 4 + 3] += b; ls2[f * 4 + 3] += b * b;
            }
        }
    }
    if (STATS) {
        #pragma unroll
        for (int c = 0; c < 8; c++) {
            atomicAdd(&ss[c], ls[c]);
            atomicAdd(&ss2[c], ls2[c]);
        }
        __syncthreads();
        if (tid < 8) {
            atomicAdd(&g_stats[tid], (double)ss[tid]);          // slot 0
            atomicAdd(&g_stats[64 + tid], (double)ss2[tid]);
        }
    }
}

// ---------------- GEMM, 32-node tiles, W in registers ----------------
// MODE 0: xin -> bufB, epilogue *dis[node], no stats (layer 1)
// MODE 1: bufA -> bufB, fused BN stats -> slot
// MODE 2: bufB -> bufA, fused BN stats -> slot
template<int FI, int FO, int MODE>
__global__ void k_gemm2(const float* __restrict__ xin, const float* __restrict__ W,
                        int n, int slot) {
    constexpr int TILE = 32;
    constexpr int NPB = 256 / FO;        // node-slots worked concurrently
    constexpr int NPT = TILE / NPB;      // nodes per thread per tile
    __shared__ float xs[TILE * FI];
    const float* zin = (MODE == 0) ? xin : (MODE == 1 ? g_bufA : g_bufB);
    float* hout      = (MODE == 0) ? g_bufB : (MODE == 1 ? g_bufB : g_bufA);
    int tid = threadIdx.x;
    int c = tid % FO, grp = tid / FO;
    float w[FI];
    #pragma unroll
    for (int k = 0; k < FI; k++) w[k] = W[k * FO + c];
    float s1 = 0.f, s2 = 0.f;
    int ntiles = (n + TILE - 1) / TILE;
    constexpr int NV = TILE * FI / 4;
    for (int t = blockIdx.x; t < ntiles; t += gridDim.x) {
        int base = t * TILE;
        __syncthreads();
        const float4* src4 = (const float4*)(zin + (size_t)base * FI);
        float4* xs4 = (float4*)xs;
        if (base + TILE <= n) {
            #pragma unroll
            for (int i = tid; i < NV; i += 256) xs4[i] = src4[i];
        } else {
            for (int i = tid; i < NV; i += 256) {
                int node = base + (i * 4) / FI;
                xs4[i] = (node < n) ? src4[i] : make_float4(0.f, 0.f, 0.f, 0.f);
            }
        }
        __syncthreads();
        #pragma unroll
        for (int u = 0; u < NPT; u++) {
            int slotn = grp + u * NPB;
            int node = base + slotn;
            if (node < n) {
                float acc = 0.f;
                const float4* row = (const float4*)(xs + slotn * FI);
                #pragma unroll
                for (int k4 = 0; k4 < FI / 4; k4++) {
                    float4 z4 = row[k4];
                    acc = fmaf(z4.x, w[k4 * 4 + 0], acc);
                    acc = fmaf(z4.y, w[k4 * 4 + 1], acc);
                    acc = fmaf(z4.z, w[k4 * 4 + 2], acc);
                    acc = fmaf(z4.w, w[k4 * 4 + 3], acc);
                }
                if (MODE == 0) {
                    hout[(size_t)node * FO + c] = acc * g_dis[node];
                } else {
                    hout[(size_t)node * FO + c] = acc;
                    s1 += acc; s2 += acc * acc;
                }
            }
        }
    }
    if (MODE != 0) {
        __shared__ float r1[256], r2[256];
        r1[tid] = s1; r2[tid] = s2;
        __syncthreads();
        if (tid < FO) {
            float a = 0.f, b = 0.f;
            #pragma unroll
            for (int k = 0; k < NPB; k++) { a += r1[k * FO + tid]; b += r2[k * FO + tid]; }
            atomicAdd(&g_stats[slot * 128 + tid], (double)a);
            atomicAdd(&g_stats[slot * 128 + 64 + tid], (double)b);
        }
    }
}

// ---------------- segment multi-aggregation (batch_idx sorted, coalesced float4) ----------------
// Applies layer-5 BN affine computed in-block from stats slot 4.
__global__ void k_segagg(const int* __restrict__ bidx, int n,
                         const float* __restrict__ gg, const float* __restrict__ bee) {
    int s = blockIdx.x;
    int tid = threadIdx.x;
    int lane = tid & 15;    // float4 channel chunk
    int rowg = tid >> 4;    // 0..15
    __shared__ int se[2];
    __shared__ __align__(16) float sc_s[64], sh_s[64];
    if (tid < 2) {
        int target = s + tid;
        int lo = 0, hi = n;
        while (lo < hi) { int m = (lo + hi) >> 1; if (bidx[m] < target) lo = m + 1; else hi = m; }
        se[tid] = lo;
    }
    if (tid < 64) {
        float sc, sh;
        bn_affine(4, tid, n, gg, bee, sc, sh);
        sc_s[tid] = sc; sh_s[tid] = sh;
    }
    __syncthreads();
    int start = se[0], end = se[1];
    float4 sc = ((const float4*)sc_s)[lane];
    float4 sh = ((const float4*)sh_s)[lane];
    float4 sum = make_float4(0.f, 0.f, 0.f, 0.f);
    float4 sum2 = make_float4(0.f, 0.f, 0.f, 0.f);
    float4 mn = make_float4(INFINITY, INFINITY, INFINITY, INFINITY);
    float4 mx = make_float4(-INFINITY, -INFINITY, -INFINITY, -INFINITY);
    const float4* in = (const float4*)g_bufA;
    for (int r = start + rowg; r < end; r += 16) {
        float4 v = in[(size_t)r * 16 + lane];
        float a0 = fmaf(sc.x, v.x, sh.x);
        float a1 = fmaf(sc.y, v.y, sh.y);
        float a2 = fmaf(sc.z, v.z, sh.z);
        float a3 = fmaf(sc.w, v.w, sh.w);
        sum.x += a0; sum2.x += a0 * a0; mn.x = fminf(mn.x, a0); mx.x = fmaxf(mx.x, a0);
        sum.y += a1; sum2.y += a1 * a1; mn.y = fminf(mn.y, a1); mx.y = fmaxf(mx.y, a1);
        sum.z += a2; sum2.z += a2 * a2; mn.z = fminf(mn.z, a2); mx.z = fmaxf(mx.z, a2);
        sum.w += a3; sum2.w += a3 * a3; mn.w = fminf(mn.w, a3); mx.w = fmaxf(mx.w, a3);
    }
    __shared__ float4 rs1[256], rs2[256], rmn[256], rmx[256];
    rs1[tid] = sum; rs2[tid] = sum2; rmn[tid] = mn; rmx[tid] = mx;
    __syncthreads();
    if (rowg == 0) {
        #pragma unroll
        for (int k = 1; k < 16; k++) {
            float4 a = rs1[k * 16 + lane], b = rs2[k * 16 + lane];
            float4 c = rmn[k * 16 + lane], d = rmx[k * 16 + lane];
            sum.x += a.x; sum.y += a.y; sum.z += a.z; sum.w += a.w;
            sum2.x += b.x; sum2.y += b.y; sum2.z += b.z; sum2.w += b.w;
            mn.x = fminf(mn.x, c.x); mn.y = fminf(mn.y, c.y);
            mn.z = fminf(mn.z, c.z); mn.w = fminf(mn.w, c.w);
            mx.x = fmaxf(mx.x, d.x); mx.y = fmaxf(mx.y, d.y);
            mx.z = fmaxf(mx.z, d.z); mx.w = fmaxf(mx.w, d.w);
        }
        float cnt = fmaxf((float)(end - start), 1.0f);
        float inv = 1.0f / cnt;
        float4 mean, stdv;
        mean.x = sum.x * inv; mean.y = sum.y * inv;
        mean.z = sum.z * inv; mean.w = sum.w * inv;
        stdv.x = sqrtf(fmaxf(sum2.x * inv - mean.x * mean.x, 0.f) + 1e-5f);
        stdv.y = sqrtf(fmaxf(sum2.y * inv - mean.y * mean.y, 0.f) + 1e-5f);
        stdv.z = sqrtf(fmaxf(sum2.z * inv - mean.z * mean.z, 0.f) + 1e-5f);
        stdv.w = sqrtf(fmaxf(sum2.w * inv - mean.w * mean.w, 0.f) + 1e-5f);
        float4* sf = (float4*)&g_segfeat[s * 256];
        sf[lane]      = mean;
        sf[16 + lane] = mn;
        sf[32 + lane] = mx;
        sf[48 + lane] = stdv;
    }
}

// ---------------- projection: [S,256] @ Wp[256,64] + bp ----------------
__global__ void k_proj(const float* __restrict__ Wp, const float* __restrict__ bp) {
    int idx = blockIdx.x * blockDim.x + threadIdx.x;
    if (idx >= S_SEG * 64) return;
    int s = idx >> 6, c = idx & 63;
    float acc = bp[c];
    const float* f = &g_segfeat[s * 256];
    #pragma unroll 8
    for (int k = 0; k < 256; k++)
        acc = fmaf(f[k], Wp[k * 64 + c], acc);
    g_proj[idx] = acc;
}

// ---------------- pack: out[b,c,j,i] = proj[offs[b] + i*14+j, c] (masked) ----------------
__global__ void k_pack(const int* __restrict__ num_sp, float* __restrict__ out) {
    int idx = blockIdx.x * blockDim.x + threadIdx.x;
    if (idx >= B_IMG * 64 * 196) return;
    int b   = idx / (64 * 196);
    int rem = idx - b * (64 * 196);
    int c   = rem / 196;
    int ji  = rem - c * 196;
    int j = ji / 14, ii = ji - j * 14;
    int p = ii * 14 + j;
    int ns = num_sp[b];
    int off = 0;
    for (int q = 0; q < b; q++) off += num_sp[q];
    float v = 0.f;
    if (p < ns) {
        int row = off + p;
        if (row > S_SEG - 1) row = S_SEG - 1;
        v = g_proj[row * 64 + c];
    }
    out[idx] = v;
}

// ---------------- host orchestration ----------------
extern "C" void kernel_launch(void* const* d_in, const int* in_sizes, int n_in,
                              void* d_out, int out_size) {
    const float* x        = (const float*)d_in[0];
    const int*   ei       = (const int*)d_in[1];
    const int*   batchidx = (const int*)d_in[2];
    const int*   num_sp   = (const int*)d_in[3];
    const int n = in_sizes[2];
    const int e = in_sizes[1] / 2;
    const int* src = ei;
    const int* dst = ei + e;

    const float* W[5], *g[5], *be[5];
    for (int i = 0; i < 5; i++) {
        W[i]  = (const float*)d_in[4 + 4 * i];
        g[i]  = (const float*)d_in[6 + 4 * i];
        be[i] = (const float*)d_in[7 + 4 * i];
    }
    const float* Wp = (const float*)d_in[24];
    const float* bp = (const float*)d_in[25];
    float* out = (float*)d_out;

    // degrees + CSR build (once per launch)
    k_zero_nodes<<<(n + 255) / 256, 256>>>(n);
    k_deg_count<<<(e + 255) / 256, 256>>>(dst, e);
    int nb = (n + SCAN_CHUNK - 1) / SCAN_CHUNK;
    k_scan1<<<nb, 256>>>(n);
    k_scan2<<<1, 512>>>(nb);
    k_scan3<<<nb, 256>>>(n, e);
    k_fill<<<(e + 255) / 256, 256>>>(src, dst, e);

    const int AB = 1184;   // agg/prep grid
    const int GB = 1184;   // gemm grid

    // L1: GEMM (24->8, writes u=t*dis to B), pure-sum agg B->A (stats slot 0 fused)
    k_gemm2<24, 8, 0><<<GB, 256>>>(x, W[0], n, 0);
    k_agg_tpn<8, false, true><<<AB, 256>>>(n);

    // L2: prep A->B (dim 8, affine from slot 0), agg B->A, gemm 8->16 A->B (slot 1)
    k_prep<8, true><<<AB, 256>>>(n, g[0], be[0], 0);
    k_agg_tpn<8, false, false><<<AB, 256>>>(n);
    k_gemm2<8, 16, 1><<<GB, 256>>>(nullptr, W[1], n, 1);

    // L3: prep B->A (dim 16, slot 1), agg A->B, gemm 16->32 B->A (slot 2)
    k_prep<16, false><<<AB, 256>>>(n, g[1], be[1], 1);
    k_agg_tpn<16, true, false><<<AB, 256>>>(n);
    k_gemm2<16, 32, 2><<<GB, 256>>>(nullptr, W[2], n, 2);

    // L4: fp16 prep A->B (dim 32, slot 2), fp16 gather B->A, gemm 32->64 A->B (slot 3)
    k_preph<32, true><<<AB, 256>>>(n, g[2], be[2], 2);
    k_aggh<32, false><<<AB, 256>>>(n);
    k_gemm2<32, 64, 1><<<GB, 256>>>(nullptr, W[3], n, 3);

    // L5: fp16 prep B->A (dim 64, slot 3), fp16 gather A->B, gemm 64->64 B->A (slot 4; h5 in A)
    k_preph<64, false><<<AB, 256>>>(n, g[3], be[3], 3);
    k_aggh<64, true><<<AB, 256>>>(n);
    k_gemm2<64, 64, 2><<<GB, 256>>>(nullptr, W[4], n, 4);

    // segment aggregation (applies L5 BN affine from slot 4, no ReLU)
    k_segagg<<<S_SEG, 256>>>(batchidx, n, g[4], be[4]);
    k_proj<<<(S_SEG * 64 + 255) / 256, 256>>>(Wp, bp);
    k_pack<<<(B_IMG * 64 * 196 + 255) / 256, 256>>>(num_sp, out);
}